// round 7
// baseline (speedup 1.0000x reference)
#include <cuda_runtime.h>
#include <cuda_bf16.h>
#include <cstdint>

#define N_RAYS_C 16384
#define RAYS_PER_BLK 2
#define NBLK (N_RAYS_C / RAYS_PER_BLK)

// ---- smem byte offsets ----
#define A1HI 0
#define A1LO 10240
#define A2HI 20480
#define A2LO 38912
#define A3HI 57344
#define A3LO 67584
#define BOFF 77824
#define B1HI 77824
#define B1LO 82944
#define B2HI 88064
#define B2LO 90368
#define B3HI 92672
#define B3LO 97792
#define B4HI 102912
#define B4LO 104064
#define BBYTES 27392
#define BIAS1 105216
#define BIAS2 105472
#define BIAS3 105536
#define SIGO  105792
#define RGBO  106304
#define SCANW 108352
#define PARTO 108368
#define SMEM_DYN 108544

// strides in bytes
#define S32 80
#define S64 144

__device__ __align__(16) unsigned char g_B[BBYTES];
__device__ float g_params[8];   // [1..3] = bc2

// ---- helpers ----
__device__ __forceinline__ uint32_t smem_u32(const void* p) {
    uint32_t a;
    asm("{ .reg .u64 t; cvta.to.shared.u64 t, %1; cvt.u32.u64 %0, t; }" : "=r"(a) : "l"(p));
    return a;
}
__device__ __forceinline__ void sts32(uint32_t a, uint32_t v) {
    asm volatile("st.shared.b32 [%0], %1;" :: "r"(a), "r"(v) : "memory");
}
__device__ __forceinline__ uint32_t lds32(uint32_t a) {
    uint32_t v; asm volatile("ld.shared.b32 %0, [%1];" : "=r"(v) : "r"(a)); return v;
}
__device__ __forceinline__ float ldsf(uint32_t a) { return __uint_as_float(lds32(a)); }
__device__ __forceinline__ void stsf(uint32_t a, float v) { sts32(a, __float_as_uint(v)); }

// hi/lo bf16 split of a value pair -> two packed stores
__device__ __forceinline__ void st_pair(uint32_t hiB, uint32_t loB, uint32_t off,
                                        float v0, float v1) {
    __nv_bfloat16 h0 = __float2bfloat16(v0), h1 = __float2bfloat16(v1);
    __nv_bfloat16 l0 = __float2bfloat16(v0 - __bfloat162float(h0));
    __nv_bfloat16 l1 = __float2bfloat16(v1 - __bfloat162float(h1));
    uint32_t hp = (uint32_t)__bfloat16_as_ushort(h0) | ((uint32_t)__bfloat16_as_ushort(h1) << 16);
    uint32_t lp = (uint32_t)__bfloat16_as_ushort(l0) | ((uint32_t)__bfloat16_as_ushort(l1) << 16);
    sts32(hiB + off, hp);
    sts32(loB + off, lp);
}

__device__ __forceinline__ void mma16816(float* d,
        uint32_t a0, uint32_t a1, uint32_t a2, uint32_t a3,
        uint32_t b0, uint32_t b1) {
    asm volatile("mma.sync.aligned.m16n8k16.row.col.f32.bf16.bf16.f32 "
        "{%0,%1,%2,%3}, {%4,%5,%6,%7}, {%8,%9}, {%0,%1,%2,%3};"
        : "+f"(d[0]), "+f"(d[1]), "+f"(d[2]), "+f"(d[3])
        : "r"(a0), "r"(a1), "r"(a2), "r"(a3), "r"(b0), "r"(b1));
}

// 3-term hi/lo split GEMM: acc[mt*NT+nt][4], M=32 rows starting at m0
template<int NT, int KT, int SA, int SB>
__device__ __forceinline__ void gemm_stage(uint32_t aHi, uint32_t aLo,
                                           uint32_t bHi, uint32_t bLo,
                                           int m0, int g, int tg, float acc[][4]) {
    #pragma unroll
    for (int i = 0; i < 2 * NT; ++i)
        acc[i][0] = acc[i][1] = acc[i][2] = acc[i][3] = 0.0f;
    #pragma unroll
    for (int term = 0; term < 3; ++term) {
        const uint32_t A = (term == 1) ? aLo : aHi;
        const uint32_t B = (term == 2) ? bLo : bHi;
        #pragma unroll
        for (int k = 0; k < KT; ++k) {
            const uint32_t kb = (uint32_t)(k * 32 + tg * 4);
            const uint32_t r0 = A + (uint32_t)((m0 + g) * SA) + kb;
            const uint32_t r1 = A + (uint32_t)((m0 + 8 + g) * SA) + kb;
            const uint32_t r2 = A + (uint32_t)((m0 + 16 + g) * SA) + kb;
            const uint32_t r3 = A + (uint32_t)((m0 + 24 + g) * SA) + kb;
            const uint32_t a00 = lds32(r0),      a01 = lds32(r1);
            const uint32_t a02 = lds32(r0 + 16), a03 = lds32(r1 + 16);
            const uint32_t a10 = lds32(r2),      a11 = lds32(r3);
            const uint32_t a12 = lds32(r2 + 16), a13 = lds32(r3 + 16);
            #pragma unroll
            for (int nt = 0; nt < NT; ++nt) {
                const uint32_t bp = B + (uint32_t)((nt * 8 + g) * SB) + kb;
                const uint32_t b0 = lds32(bp), b1 = lds32(bp + 16);
                mma16816(acc[nt],      a00, a01, a02, a03, b0, b1);
                mma16816(acc[NT + nt], a10, a11, a12, a13, b0, b1);
            }
        }
    }
}

// ---- setup: build hi/lo weight image in [n][k]-padded layouts ----
__global__ void k_setup(const float* __restrict__ W1, const float* __restrict__ W2,
                        const float* __restrict__ Wc1, const float* __restrict__ Wc2,
                        const float* __restrict__ bc2) {
    const int tid = blockIdx.x * blockDim.x + threadIdx.x;
    if (tid == 0) { g_params[1] = bc2[0]; g_params[2] = bc2[1]; g_params[3] = bc2[2]; }
    // B1: 64 x 40, B2: 16 x 72, B3: 64 x 40, B4: 8 x 72
    const int n1 = 64 * 40, n2 = 16 * 72, n3 = 64 * 40, n4 = 8 * 72;
    for (int i = tid; i < n1 + n2 + n3 + n4; i += blockDim.x * gridDim.x) {
        float v; int hiOff, loOff;
        if (i < n1) {
            int n = i / 40, k = i % 40;
            v = (k < 27) ? W1[k * 64 + n] : 0.0f;
            hiOff = (B1HI - BOFF) + i * 2; loOff = (B1LO - BOFF) + i * 2;
        } else if (i < n1 + n2) {
            int j = i - n1, n = j / 72, k = j % 72;
            v = (k < 64) ? W2[k * 16 + n] : 0.0f;
            hiOff = (B2HI - BOFF) + j * 2; loOff = (B2LO - BOFF) + j * 2;
        } else if (i < n1 + n2 + n3) {
            int j = i - n1 - n2, n = j / 40, k = j % 40;
            v = (k >= 1 && k < 20) ? Wc1[(k - 1) * 64 + n] : 0.0f;
            hiOff = (B3HI - BOFF) + j * 2; loOff = (B3LO - BOFF) + j * 2;
        } else {
            int j = i - n1 - n2 - n3, n = j / 72, k = j % 72;
            v = (n < 3 && k < 64) ? Wc2[k * 3 + n] : 0.0f;
            hiOff = (B4HI - BOFF) + j * 2; loOff = (B4LO - BOFF) + j * 2;
        }
        __nv_bfloat16 hi = __float2bfloat16(v);
        __nv_bfloat16 lo = __float2bfloat16(v - __bfloat162float(hi));
        *(__nv_bfloat16*)(g_B + hiOff) = hi;
        *(__nv_bfloat16*)(g_B + loOff) = lo;
    }
}

// ---- render ----
__global__ void __launch_bounds__(128) nerf_mma_kernel(
    const float* __restrict__ rays_o, const float* __restrict__ rays_d,
    const float* __restrict__ tnoise, const float* __restrict__ aabb,
    const float* __restrict__ b1, const float* __restrict__ b2,
    const float* __restrict__ bc1, float* __restrict__ out) {
    extern __shared__ __align__(16) unsigned char sm[];
    const uint32_t base = smem_u32(sm);
    const int tid = threadIdx.x, lane = tid & 31, wid = tid >> 5;
    const int g = lane >> 2, tg = lane & 3;
    const int m0 = wid * 32;

    // prologue: weights + biases + A3 zero pad (cols 20..31)
    {
        const int4* src = (const int4*)g_B;
        int4* dst = (int4*)(sm + BOFF);
        for (int i = tid; i < BBYTES / 16; i += 128) dst[i] = src[i];
        if (tid < 64) stsf(base + BIAS1 + 4 * tid, b1[tid]);
        if (tid < 16) stsf(base + BIAS2 + 4 * tid, b2[tid]);
        if (tid >= 64) stsf(base + BIAS3 + 4 * (tid - 64), bc1[tid - 64]);
        #pragma unroll
        for (int j = 0; j < 6; ++j) {
            sts32(base + A3HI + (uint32_t)tid * S32 + 40 + 4 * j, 0u);
            sts32(base + A3LO + (uint32_t)tid * S32 + 40 + 4 * j, 0u);
        }
    }
    const float ax0 = aabb[0], ay0 = aabb[1], az0 = aabb[2];
    const float ax1 = aabb[3], ay1 = aabb[4], az1 = aabb[5];
    const float p1 = g_params[1], p2 = g_params[2], p3 = g_params[3];

    float acc[16][4];

    for (int rr = 0; rr < RAYS_PER_BLK; ++rr) {
        const int ray = blockIdx.x * RAYS_PER_BLK + rr;

        // ---- ray setup (thread = sample tid) ----
        const float ox = rays_o[3 * ray], oy = rays_o[3 * ray + 1], oz = rays_o[3 * ray + 2];
        const float dx = rays_d[3 * ray], dy = rays_d[3 * ray + 1], dz = rays_d[3 * ray + 2];
        const float ix = 1.0f / dx, iy = 1.0f / dy, iz = 1.0f / dz;
        const float t0x = (ax0 - ox) * ix, t1x = (ax1 - ox) * ix;
        const float t0y = (ay0 - oy) * iy, t1y = (ay1 - oy) * iy;
        const float t0z = (az0 - oz) * iz, t1z = (az1 - oz) * iz;
        float tn = fmaxf(fmaxf(fminf(t0x, t1x), fminf(t0y, t1y)), fminf(t0z, t1z));
        tn = fmaxf(tn, 0.0f);
        float tf = fminf(fminf(fmaxf(t0x, t1x), fmaxf(t0y, t1y)), fmaxf(t0z, t1z));
        float act;
        if (tf > tn) { act = 1.0f; } else { act = 0.0f; tn = 0.0f; tf = 0.0f; }
        const float span = tf - tn;
        const float dnorm = sqrtf(dx * dx + dy * dy + dz * dz);

        const float n0 = tnoise[tid * N_RAYS_C + ray];
        const float n1 = (tid < 127) ? tnoise[(tid + 1) * N_RAYS_C + ray] : 0.0f;
        const float ts  = tn + span * (((float)tid + n0) * (1.0f / 128.0f));
        const float ts1 = tn + span * (((float)tid + 1.0f + n1) * (1.0f / 128.0f));
        const float delta = (tid < 127) ? (ts1 - ts) : (tf * 10.0f - ts);

        {   // posenc -> A1 row tid (cols 0..31, 28..31 zero)
            float e[28];
            const float px = ox + ts * dx, py = oy + ts * dy, pz = oz + ts * dz;
            const float xnx = 2.0f * (px - ax0) / (ax1 - ax0) - 1.0f;
            const float xny = 2.0f * (py - ay0) / (ay1 - ay0) - 1.0f;
            const float xnz = 2.0f * (pz - az0) / (az1 - az0) - 1.0f;
            e[0] = xnx; e[1] = xny; e[2] = xnz;
            float f = 3.14159265358979323846f;
            #pragma unroll
            for (int k = 0; k < 4; ++k) {
                float sx, cx, sy, cy, sz, cz;
                __sincosf(f * xnx, &sx, &cx);
                __sincosf(f * xny, &sy, &cy);
                __sincosf(f * xnz, &sz, &cz);
                e[3 + 6 * k + 0] = sx; e[3 + 6 * k + 1] = sy; e[3 + 6 * k + 2] = sz;
                e[6 + 6 * k + 0] = cx; e[6 + 6 * k + 1] = cy; e[6 + 6 * k + 2] = cz;
                f *= 2.0f;
            }
            e[27] = 0.0f;
            const uint32_t rb = (uint32_t)tid * S32;
            #pragma unroll
            for (int p = 0; p < 14; ++p)
                st_pair(base + A1HI, base + A1LO, rb + 4 * p, e[2 * p], e[2 * p + 1]);
            st_pair(base + A1HI, base + A1LO, rb + 56, 0.0f, 0.0f);
            st_pair(base + A1HI, base + A1LO, rb + 60, 0.0f, 0.0f);
            // ynm -> A3 row tid cols 16..19
            const float idn = 1.0f / dnorm;
            const float c1 = 0.4886025119029199f;
            st_pair(base + A3HI, base + A3LO, rb + 32, 0.28209479177387814f, c1 * dy * idn);
            st_pair(base + A3HI, base + A3LO, rb + 36, c1 * dz * idn, c1 * dx * idn);
        }
        __syncthreads();

        // ---- stage 1: posenc @ W1, relu, -> A2 ----
        gemm_stage<8, 2, S32, S32>(base + A1HI, base + A1LO, base + B1HI, base + B1LO,
                                   m0, g, tg, acc);
        #pragma unroll
        for (int nt = 0; nt < 8; ++nt) {
            const int c = nt * 8 + tg * 2;
            const float bb0 = ldsf(base + BIAS1 + 4 * c);
            const float bb1 = ldsf(base + BIAS1 + 4 * c + 4);
            #pragma unroll
            for (int mt = 0; mt < 2; ++mt) {
                float* d = acc[mt * 8 + nt];
                const int rA = m0 + mt * 16 + g, rB = rA + 8;
                st_pair(base + A2HI, base + A2LO, (uint32_t)(rA * S64 + c * 2),
                        fmaxf(d[0] + bb0, 0.f), fmaxf(d[1] + bb1, 0.f));
                st_pair(base + A2HI, base + A2LO, (uint32_t)(rB * S64 + c * 2),
                        fmaxf(d[2] + bb0, 0.f), fmaxf(d[3] + bb1, 0.f));
            }
        }
        __syncthreads();

        // ---- stage 2: h @ W2 (N=16), raw -> A3 cols 0..15, sigma col0 ----
        gemm_stage<2, 4, S64, S64>(base + A2HI, base + A2LO, base + B2HI, base + B2LO,
                                   m0, g, tg, acc);
        #pragma unroll
        for (int nt = 0; nt < 2; ++nt) {
            const int c = nt * 8 + tg * 2;
            const float bb0 = ldsf(base + BIAS2 + 4 * c);
            const float bb1 = ldsf(base + BIAS2 + 4 * c + 4);
            #pragma unroll
            for (int mt = 0; mt < 2; ++mt) {
                float* d = acc[mt * 2 + nt];
                const int rA = m0 + mt * 16 + g, rB = rA + 8;
                const float v0 = d[0] + bb0, v1 = d[1] + bb1;
                const float v2 = d[2] + bb0, v3 = d[3] + bb1;
                st_pair(base + A3HI, base + A3LO, (uint32_t)(rA * S32 + c * 2), v0, v1);
                st_pair(base + A3HI, base + A3LO, (uint32_t)(rB * S32 + c * 2), v2, v3);
                if (nt == 0 && tg == 0) {
                    stsf(base + SIGO + 4 * rA, v0);
                    stsf(base + SIGO + 4 * rB, v2);
                }
            }
        }
        __syncthreads();

        // ---- stage 3: in2 @ Wc1 (perm), relu, -> A2 ----
        gemm_stage<8, 2, S32, S32>(base + A3HI, base + A3LO, base + B3HI, base + B3LO,
                                   m0, g, tg, acc);
        #pragma unroll
        for (int nt = 0; nt < 8; ++nt) {
            const int c = nt * 8 + tg * 2;
            const float bb0 = ldsf(base + BIAS3 + 4 * c);
            const float bb1 = ldsf(base + BIAS3 + 4 * c + 4);
            #pragma unroll
            for (int mt = 0; mt < 2; ++mt) {
                float* d = acc[mt * 8 + nt];
                const int rA = m0 + mt * 16 + g, rB = rA + 8;
                st_pair(base + A2HI, base + A2LO, (uint32_t)(rA * S64 + c * 2),
                        fmaxf(d[0] + bb0, 0.f), fmaxf(d[1] + bb1, 0.f));
                st_pair(base + A2HI, base + A2LO, (uint32_t)(rB * S64 + c * 2),
                        fmaxf(d[2] + bb0, 0.f), fmaxf(d[3] + bb1, 0.f));
            }
        }
        __syncthreads();

        // ---- stage 4: hc @ Wc2 (N=8), raw -> rgb buffer ----
        gemm_stage<1, 4, S64, S64>(base + A2HI, base + A2LO, base + B4HI, base + B4LO,
                                   m0, g, tg, acc);
        if (tg < 2) {
            #pragma unroll
            for (int mt = 0; mt < 2; ++mt) {
                float* d = acc[mt];
                const int rA = m0 + mt * 16 + g, rB = rA + 8;
                stsf(base + RGBO + rA * 16 + tg * 8,     d[0]);
                stsf(base + RGBO + rA * 16 + tg * 8 + 4, d[1]);
                stsf(base + RGBO + rB * 16 + tg * 8,     d[2]);
                stsf(base + RGBO + rB * 16 + tg * 8 + 4, d[3]);
            }
        }
        __syncthreads();

        // ---- transmittance scan + composite (thread = sample tid) ----
        const float sigma = __expf(ldsf(base + SIGO + 4 * tid));
        const float sd = sigma * delta * dnorm;
        float x = sd;
        #pragma unroll
        for (int off = 1; off < 32; off <<= 1) {
            float v = __shfl_up_sync(0xffffffffu, x, off);
            if (lane >= off) x += v;
        }
        if (lane == 31) stsf(base + SCANW + 4 * wid, x);
        __syncthreads();
        float pre = 0.0f;
        #pragma unroll
        for (int w = 0; w < 4; ++w) if (w < wid) pre += ldsf(base + SCANW + 4 * w);
        const float excl = (x + pre) - sd;
        const float trans = __expf(-excl);
        const float alpha = 1.0f - __expf(-sd);
        const float wgt = trans * alpha * act;

        const float rC = 1.0f / (1.0f + __expf(-(ldsf(base + RGBO + tid * 16)     + p1)));
        const float gC = 1.0f / (1.0f + __expf(-(ldsf(base + RGBO + tid * 16 + 4) + p2)));
        const float bC = 1.0f / (1.0f + __expf(-(ldsf(base + RGBO + tid * 16 + 8) + p3)));

        float cr = wgt * rC, cg = wgt * gC, cb = wgt * bC, ca = wgt;
        #pragma unroll
        for (int off = 16; off > 0; off >>= 1) {
            cr += __shfl_xor_sync(0xffffffffu, cr, off);
            cg += __shfl_xor_sync(0xffffffffu, cg, off);
            cb += __shfl_xor_sync(0xffffffffu, cb, off);
            ca += __shfl_xor_sync(0xffffffffu, ca, off);
        }
        if (lane == 0) {
            stsf(base + PARTO + (wid * 4 + 0) * 4, cr);
            stsf(base + PARTO + (wid * 4 + 1) * 4, cg);
            stsf(base + PARTO + (wid * 4 + 2) * 4, cb);
            stsf(base + PARTO + (wid * 4 + 3) * 4, ca);
        }
        __syncthreads();
        if (tid == 0) {
            float4 o4 = make_float4(0.f, 0.f, 0.f, 0.f);
            #pragma unroll
            for (int w = 0; w < 4; ++w) {
                o4.x += ldsf(base + PARTO + (w * 4 + 0) * 4);
                o4.y += ldsf(base + PARTO + (w * 4 + 1) * 4);
                o4.z += ldsf(base + PARTO + (w * 4 + 2) * 4);
                o4.w += ldsf(base + PARTO + (w * 4 + 3) * 4);
            }
            *(float4*)(out + ray * 4) = o4;
        }
        __syncthreads();
    }
}

extern "C" void kernel_launch(void* const* d_in, const int* in_sizes, int n_in,
                              void* d_out, int out_size) {
    const float* rays_o = (const float*)d_in[0];
    const float* rays_d = (const float*)d_in[1];
    const float* tnoise = (const float*)d_in[2];
    const float* aabb   = (const float*)d_in[3];
    const float* W1     = (const float*)d_in[4];
    const float* b1     = (const float*)d_in[5];
    const float* W2     = (const float*)d_in[6];
    const float* b2     = (const float*)d_in[7];
    const float* Wc1    = (const float*)d_in[8];
    const float* bc1    = (const float*)d_in[9];
    const float* Wc2    = (const float*)d_in[10];
    const float* bc2    = (const float*)d_in[11];
    float* out = (float*)d_out;

    k_setup<<<8, 256>>>(W1, W2, Wc1, Wc2, bc2);
    cudaFuncSetAttribute(nerf_mma_kernel, cudaFuncAttributeMaxDynamicSharedMemorySize, SMEM_DYN);
    nerf_mma_kernel<<<NBLK, 128, SMEM_DYN>>>(rays_o, rays_d, tnoise, aabb,
                                             b1, b2, bc1, out);
}

// round 8
// speedup vs baseline: 1.0524x; 1.0524x over previous
#include <cuda_runtime.h>
#include <cuda_bf16.h>
#include <cstdint>

#define N_RAYS_C 16384
#define RAYS_PER_BLK 2
#define NBLK (N_RAYS_C / RAYS_PER_BLK)

// ---- smem byte offsets ----
#define A32HI 0
#define A32LO 10240
#define A64HI 20480
#define A64LO 38912
#define BOFF  57344
#define B1HI  (BOFF + 0)
#define B1LO  (BOFF + 5120)
#define B2HI  (BOFF + 10240)
#define B2LO  (BOFF + 12544)
#define B3HI  (BOFF + 14848)
#define B3LO  (BOFF + 19968)
#define B4HI  (BOFF + 25088)
#define B4LO  (BOFF + 26240)
#define BBYTES 27392
#define BIAS1 (BOFF + BBYTES)          // 84736, 64 floats
#define BIAS2 (BIAS1 + 256)            // 16 floats
#define BIAS3 (BIAS2 + 64)             // 64 floats
#define SIGO  (BIAS3 + 256)            // 128 floats
#define RGBO  (SIGO + 512)             // 128 x 16B
#define SCANW (RGBO + 2048)
#define PARTO (SCANW + 16)
#define SMEM_DYN 88064

// strides in bytes
#define S32 80
#define S64 144

__device__ __align__(16) unsigned char g_B[BBYTES];
__device__ float g_params[8];   // [1..3] = bc2

// ---- helpers ----
__device__ __forceinline__ uint32_t smem_u32(const void* p) {
    uint32_t a;
    asm("{ .reg .u64 t; cvta.to.shared.u64 t, %1; cvt.u32.u64 %0, t; }" : "=r"(a) : "l"(p));
    return a;
}
__device__ __forceinline__ void sts32(uint32_t a, uint32_t v) {
    asm volatile("st.shared.b32 [%0], %1;" :: "r"(a), "r"(v) : "memory");
}
__device__ __forceinline__ void sts64z(uint32_t a) {
    asm volatile("st.shared.v2.b32 [%0], {%1, %2};" :: "r"(a), "r"(0u), "r"(0u) : "memory");
}
__device__ __forceinline__ uint32_t lds32(uint32_t a) {
    uint32_t v; asm volatile("ld.shared.b32 %0, [%1];" : "=r"(v) : "r"(a)); return v;
}
__device__ __forceinline__ float ldsf(uint32_t a) { return __uint_as_float(lds32(a)); }
__device__ __forceinline__ void stsf(uint32_t a, float v) { sts32(a, __float_as_uint(v)); }

__device__ __forceinline__ void ldm_x4(uint32_t addr, uint32_t* r) {
    asm volatile("ldmatrix.sync.aligned.m8n8.x4.shared.b16 {%0,%1,%2,%3}, [%4];"
        : "=r"(r[0]), "=r"(r[1]), "=r"(r[2]), "=r"(r[3]) : "r"(addr));
}
__device__ __forceinline__ void ldm_x2(uint32_t addr, uint32_t* r) {
    asm volatile("ldmatrix.sync.aligned.m8n8.x2.shared.b16 {%0,%1}, [%2];"
        : "=r"(r[0]), "=r"(r[1]) : "r"(addr));
}

// hi/lo bf16 split of a value pair -> two packed stores
__device__ __forceinline__ void st_pair(uint32_t hiB, uint32_t loB, uint32_t off,
                                        float v0, float v1) {
    __nv_bfloat16 h0 = __float2bfloat16(v0), h1 = __float2bfloat16(v1);
    __nv_bfloat16 l0 = __float2bfloat16(v0 - __bfloat162float(h0));
    __nv_bfloat16 l1 = __float2bfloat16(v1 - __bfloat162float(h1));
    uint32_t hp = (uint32_t)__bfloat16_as_ushort(h0) | ((uint32_t)__bfloat16_as_ushort(h1) << 16);
    uint32_t lp = (uint32_t)__bfloat16_as_ushort(l0) | ((uint32_t)__bfloat16_as_ushort(l1) << 16);
    sts32(hiB + off, hp);
    sts32(loB + off, lp);
}

__device__ __forceinline__ void mma16816(float* d,
        uint32_t a0, uint32_t a1, uint32_t a2, uint32_t a3,
        uint32_t b0, uint32_t b1) {
    asm volatile("mma.sync.aligned.m16n8k16.row.col.f32.bf16.bf16.f32 "
        "{%0,%1,%2,%3}, {%4,%5,%6,%7}, {%8,%9}, {%0,%1,%2,%3};"
        : "+f"(d[0]), "+f"(d[1]), "+f"(d[2]), "+f"(d[3])
        : "r"(a0), "r"(a1), "r"(a2), "r"(a3), "r"(b0), "r"(b1));
}

// 3-term hi/lo split GEMM via ldmatrix. acc[mt*NT+nt][4]. M=32 rows at m0.
template<int NT, int KT, int SA, int SB>
__device__ __forceinline__ void gemm_ldm(uint32_t aHi, uint32_t aLo,
                                         uint32_t bHi, uint32_t bLo,
                                         int m0, int lane, float acc[][4]) {
    #pragma unroll
    for (int i = 0; i < 2 * NT; ++i)
        acc[i][0] = acc[i][1] = acc[i][2] = acc[i][3] = 0.0f;
    const uint32_t aoff = (uint32_t)((m0 + (lane & 7) + ((lane >> 3) & 1) * 8) * SA
                                     + (lane >> 4) * 16);
    const uint32_t boff = (uint32_t)(((lane & 7) + ((lane >> 4) & 1) * 8) * SB
                                     + ((lane >> 3) & 1) * 16);
    const uint32_t b2off = (uint32_t)((lane & 7) * SB + ((lane >> 3) & 1) * 16);
    #pragma unroll
    for (int kk = 0; kk < KT; ++kk) {
        uint32_t ah[8], al[8];
        ldm_x4(aHi + aoff + kk * 32, ah);
        ldm_x4(aHi + aoff + 16 * SA + kk * 32, ah + 4);
        ldm_x4(aLo + aoff + kk * 32, al);
        ldm_x4(aLo + aoff + 16 * SA + kk * 32, al + 4);
        if (NT == 1) {
            uint32_t bh[2], bl[2];
            ldm_x2(bHi + b2off + kk * 32, bh);
            mma16816(acc[0], ah[0], ah[1], ah[2], ah[3], bh[0], bh[1]);
            mma16816(acc[1], ah[4], ah[5], ah[6], ah[7], bh[0], bh[1]);
            mma16816(acc[0], al[0], al[1], al[2], al[3], bh[0], bh[1]);
            mma16816(acc[1], al[4], al[5], al[6], al[7], bh[0], bh[1]);
            ldm_x2(bLo + b2off + kk * 32, bl);
            mma16816(acc[0], ah[0], ah[1], ah[2], ah[3], bl[0], bl[1]);
            mma16816(acc[1], ah[4], ah[5], ah[6], ah[7], bl[0], bl[1]);
        } else {
            #pragma unroll
            for (int np = 0; np < NT / 2; ++np) {
                uint32_t bh[4], bl[4];
                const uint32_t bo = boff + (uint32_t)(np * 16 * SB) + kk * 32;
                ldm_x4(bHi + bo, bh);
                mma16816(acc[2 * np],          ah[0], ah[1], ah[2], ah[3], bh[0], bh[1]);
                mma16816(acc[NT + 2 * np],     ah[4], ah[5], ah[6], ah[7], bh[0], bh[1]);
                mma16816(acc[2 * np + 1],      ah[0], ah[1], ah[2], ah[3], bh[2], bh[3]);
                mma16816(acc[NT + 2 * np + 1], ah[4], ah[5], ah[6], ah[7], bh[2], bh[3]);
                mma16816(acc[2 * np],          al[0], al[1], al[2], al[3], bh[0], bh[1]);
                mma16816(acc[NT + 2 * np],     al[4], al[5], al[6], al[7], bh[0], bh[1]);
                mma16816(acc[2 * np + 1],      al[0], al[1], al[2], al[3], bh[2], bh[3]);
                mma16816(acc[NT + 2 * np + 1], al[4], al[5], al[6], al[7], bh[2], bh[3]);
                ldm_x4(bLo + bo, bl);
                mma16816(acc[2 * np],          ah[0], ah[1], ah[2], ah[3], bl[0], bl[1]);
                mma16816(acc[NT + 2 * np],     ah[4], ah[5], ah[6], ah[7], bl[0], bl[1]);
                mma16816(acc[2 * np + 1],      ah[0], ah[1], ah[2], ah[3], bl[2], bl[3]);
                mma16816(acc[NT + 2 * np + 1], ah[4], ah[5], ah[6], ah[7], bl[2], bl[3]);
            }
        }
    }
}

// ---- setup: build hi/lo weight image in [n][k]-padded layouts ----
__global__ void k_setup(const float* __restrict__ W1, const float* __restrict__ W2,
                        const float* __restrict__ Wc1, const float* __restrict__ Wc2,
                        const float* __restrict__ bc2) {
    const int tid = blockIdx.x * blockDim.x + threadIdx.x;
    if (tid == 0) { g_params[1] = bc2[0]; g_params[2] = bc2[1]; g_params[3] = bc2[2]; }
    const int n1 = 64 * 40, n2 = 16 * 72, n3 = 64 * 40, n4 = 8 * 72;
    for (int i = tid; i < n1 + n2 + n3 + n4; i += blockDim.x * gridDim.x) {
        float v; int hiOff, loOff;
        if (i < n1) {
            int n = i / 40, k = i % 40;
            v = (k < 27) ? W1[k * 64 + n] : 0.0f;
            hiOff = (B1HI - BOFF) + i * 2; loOff = (B1LO - BOFF) + i * 2;
        } else if (i < n1 + n2) {
            int j = i - n1, n = j / 72, k = j % 72;
            v = (k < 64) ? W2[k * 16 + n] : 0.0f;
            hiOff = (B2HI - BOFF) + j * 2; loOff = (B2LO - BOFF) + j * 2;
        } else if (i < n1 + n2 + n3) {
            int j = i - n1 - n2, n = j / 40, k = j % 40;
            v = (k >= 1 && k < 20) ? Wc1[(k - 1) * 64 + n] : 0.0f;
            hiOff = (B3HI - BOFF) + j * 2; loOff = (B3LO - BOFF) + j * 2;
        } else {
            int j = i - n1 - n2 - n3, n = j / 72, k = j % 72;
            v = (n < 3 && k < 64) ? Wc2[k * 3 + n] : 0.0f;
            hiOff = (B4HI - BOFF) + j * 2; loOff = (B4LO - BOFF) + j * 2;
        }
        __nv_bfloat16 hi = __float2bfloat16(v);
        __nv_bfloat16 lo = __float2bfloat16(v - __bfloat162float(hi));
        *(__nv_bfloat16*)(g_B + hiOff) = hi;
        *(__nv_bfloat16*)(g_B + loOff) = lo;
    }
}

// ---- render ----
__global__ void __launch_bounds__(128) nerf_mma2_kernel(
    const float* __restrict__ rays_o, const float* __restrict__ rays_d,
    const float* __restrict__ tnoise, const float* __restrict__ aabb,
    const float* __restrict__ b1, const float* __restrict__ b2,
    const float* __restrict__ bc1, float* __restrict__ out) {
    extern __shared__ __align__(16) unsigned char sm[];
    const uint32_t base = smem_u32(sm);
    const int tid = threadIdx.x, lane = tid & 31, wid = tid >> 5;
    const int g = lane >> 2, tg = lane & 3;
    const int m0 = wid * 32;

    // prologue: weights + biases
    {
        const int4* src = (const int4*)g_B;
        int4* dst = (int4*)(sm + (BOFF));
        for (int i = tid; i < BBYTES / 16; i += 128) dst[i] = src[i];
        if (tid < 64) stsf(base + BIAS1 + 4 * tid, b1[tid]);
        if (tid < 16) stsf(base + BIAS2 + 4 * tid, b2[tid]);
        if (tid >= 64) stsf(base + BIAS3 + 4 * (tid - 64), bc1[tid - 64]);
    }
    const float ax0 = aabb[0], ay0 = aabb[1], az0 = aabb[2];
    const float ax1 = aabb[3], ay1 = aabb[4], az1 = aabb[5];
    const float p1 = g_params[1], p2 = g_params[2], p3 = g_params[3];
    __syncthreads();

    float acc[16][4];

    for (int rr = 0; rr < RAYS_PER_BLK; ++rr) {
        const int ray = blockIdx.x * RAYS_PER_BLK + rr;

        // ---- ray setup (thread = sample tid = row tid) ----
        const float ox = rays_o[3 * ray], oy = rays_o[3 * ray + 1], oz = rays_o[3 * ray + 2];
        const float dx = rays_d[3 * ray], dy = rays_d[3 * ray + 1], dz = rays_d[3 * ray + 2];
        const float ix = 1.0f / dx, iy = 1.0f / dy, iz = 1.0f / dz;
        const float t0x = (ax0 - ox) * ix, t1x = (ax1 - ox) * ix;
        const float t0y = (ay0 - oy) * iy, t1y = (ay1 - oy) * iy;
        const float t0z = (az0 - oz) * iz, t1z = (az1 - oz) * iz;
        float tn = fmaxf(fmaxf(fminf(t0x, t1x), fminf(t0y, t1y)), fminf(t0z, t1z));
        tn = fmaxf(tn, 0.0f);
        float tf = fminf(fminf(fmaxf(t0x, t1x), fmaxf(t0y, t1y)), fmaxf(t0z, t1z));
        float act;
        if (tf > tn) { act = 1.0f; } else { act = 0.0f; tn = 0.0f; tf = 0.0f; }
        const float span = tf - tn;
        const float dnorm = sqrtf(dx * dx + dy * dy + dz * dz);

        const float n0 = tnoise[tid * N_RAYS_C + ray];
        const float n1 = (tid < 127) ? tnoise[(tid + 1) * N_RAYS_C + ray] : 0.0f;
        const float ts  = tn + span * (((float)tid + n0) * (1.0f / 128.0f));
        const float ts1 = tn + span * (((float)tid + 1.0f + n1) * (1.0f / 128.0f));
        const float delta = (tid < 127) ? (ts1 - ts) : (tf * 10.0f - ts);

        // ynm (kept in regs; stored to A32 cols 16-19 during stage-2 epilogue)
        const float idn = 1.0f / dnorm;
        const float c1 = 0.4886025119029199f;
        const float y0 = 0.28209479177387814f, y1 = c1 * dy * idn;
        const float y2 = c1 * dz * idn,        y3 = c1 * dx * idn;

        {   // posenc -> A32 row tid (cols 0..27 values, 28..31 zero)
            float e[28];
            const float px = ox + ts * dx, py = oy + ts * dy, pz = oz + ts * dz;
            const float xnx = 2.0f * (px - ax0) / (ax1 - ax0) - 1.0f;
            const float xny = 2.0f * (py - ay0) / (ay1 - ay0) - 1.0f;
            const float xnz = 2.0f * (pz - az0) / (az1 - az0) - 1.0f;
            e[0] = xnx; e[1] = xny; e[2] = xnz;
            float f = 3.14159265358979323846f;
            #pragma unroll
            for (int k = 0; k < 4; ++k) {
                float sx, cx, sy, cy, sz, cz;
                __sincosf(f * xnx, &sx, &cx);
                __sincosf(f * xny, &sy, &cy);
                __sincosf(f * xnz, &sz, &cz);
                e[3 + 6 * k + 0] = sx; e[3 + 6 * k + 1] = sy; e[3 + 6 * k + 2] = sz;
                e[6 + 6 * k + 0] = cx; e[6 + 6 * k + 1] = cy; e[6 + 6 * k + 2] = cz;
                f *= 2.0f;
            }
            e[27] = 0.0f;
            const uint32_t rb = (uint32_t)tid * S32;
            #pragma unroll
            for (int p = 0; p < 14; ++p)
                st_pair(base + A32HI, base + A32LO, rb + 4 * p, e[2 * p], e[2 * p + 1]);
            st_pair(base + A32HI, base + A32LO, rb + 56, 0.0f, 0.0f);
            st_pair(base + A32HI, base + A32LO, rb + 60, 0.0f, 0.0f);
        }
        __syncwarp();

        // ---- stage 1: posenc @ W1 (K32,N64), relu -> A64 ----
        gemm_ldm<8, 2, S32, S32>(base + A32HI, base + A32LO, base + B1HI, base + B1LO,
                                 m0, lane, acc);
        #pragma unroll
        for (int nt = 0; nt < 8; ++nt) {
            const int c = nt * 8 + tg * 2;
            const float bb0 = ldsf(base + BIAS1 + 4 * c);
            const float bb1 = ldsf(base + BIAS1 + 4 * c + 4);
            #pragma unroll
            for (int mt = 0; mt < 2; ++mt) {
                float* d = acc[mt * 8 + nt];
                const int rA = m0 + mt * 16 + g, rB = rA + 8;
                st_pair(base + A64HI, base + A64LO, (uint32_t)(rA * S64 + c * 2),
                        fmaxf(d[0] + bb0, 0.f), fmaxf(d[1] + bb1, 0.f));
                st_pair(base + A64HI, base + A64LO, (uint32_t)(rB * S64 + c * 2),
                        fmaxf(d[2] + bb0, 0.f), fmaxf(d[3] + bb1, 0.f));
            }
        }
        __syncwarp();

        // ---- stage 2: h @ W2 (K64,N16), raw -> A32 cols 0..15 ----
        gemm_ldm<2, 4, S64, S64>(base + A64HI, base + A64LO, base + B2HI, base + B2LO,
                                 m0, lane, acc);
        #pragma unroll
        for (int nt = 0; nt < 2; ++nt) {
            const int c = nt * 8 + tg * 2;
            const float bb0 = ldsf(base + BIAS2 + 4 * c);
            const float bb1 = ldsf(base + BIAS2 + 4 * c + 4);
            #pragma unroll
            for (int mt = 0; mt < 2; ++mt) {
                float* d = acc[mt * 2 + nt];
                const int rA = m0 + mt * 16 + g, rB = rA + 8;
                const float v0 = d[0] + bb0, v1 = d[1] + bb1;
                const float v2 = d[2] + bb0, v3 = d[3] + bb1;
                st_pair(base + A32HI, base + A32LO, (uint32_t)(rA * S32 + c * 2), v0, v1);
                st_pair(base + A32HI, base + A32LO, (uint32_t)(rB * S32 + c * 2), v2, v3);
                if (nt == 0 && tg == 0) {
                    stsf(base + SIGO + 4 * rA, v0);
                    stsf(base + SIGO + 4 * rB, v2);
                }
            }
        }
        {   // ynm -> cols 16-19; re-zero cols 20-27 of own row
            const uint32_t rb = (uint32_t)tid * S32;
            st_pair(base + A32HI, base + A32LO, rb + 32, y0, y1);
            st_pair(base + A32HI, base + A32LO, rb + 36, y2, y3);
            sts64z(base + A32HI + rb + 40); sts64z(base + A32HI + rb + 48);
            sts64z(base + A32LO + rb + 40); sts64z(base + A32LO + rb + 48);
        }
        __syncwarp();

        // ---- stage 3: in2 @ Wc1 (K32,N64), relu -> A64 ----
        gemm_ldm<8, 2, S32, S32>(base + A32HI, base + A32LO, base + B3HI, base + B3LO,
                                 m0, lane, acc);
        #pragma unroll
        for (int nt = 0; nt < 8; ++nt) {
            const int c = nt * 8 + tg * 2;
            const float bb0 = ldsf(base + BIAS3 + 4 * c);
            const float bb1 = ldsf(base + BIAS3 + 4 * c + 4);
            #pragma unroll
            for (int mt = 0; mt < 2; ++mt) {
                float* d = acc[mt * 8 + nt];
                const int rA = m0 + mt * 16 + g, rB = rA + 8;
                st_pair(base + A64HI, base + A64LO, (uint32_t)(rA * S64 + c * 2),
                        fmaxf(d[0] + bb0, 0.f), fmaxf(d[1] + bb1, 0.f));
                st_pair(base + A64HI, base + A64LO, (uint32_t)(rB * S64 + c * 2),
                        fmaxf(d[2] + bb0, 0.f), fmaxf(d[3] + bb1, 0.f));
            }
        }
        __syncwarp();

        // ---- stage 4: hc @ Wc2 (K64,N8), raw -> RGBO ----
        gemm_ldm<1, 4, S64, S64>(base + A64HI, base + A64LO, base + B4HI, base + B4LO,
                                 m0, lane, acc);
        if (tg < 2) {
            #pragma unroll
            for (int mt = 0; mt < 2; ++mt) {
                float* d = acc[mt];
                const int rA = m0 + mt * 16 + g, rB = rA + 8;
                stsf(base + RGBO + rA * 16 + tg * 8,     d[0]);
                stsf(base + RGBO + rA * 16 + tg * 8 + 4, d[1]);
                stsf(base + RGBO + rB * 16 + tg * 8,     d[2]);
                stsf(base + RGBO + rB * 16 + tg * 8 + 4, d[3]);
            }
        }
        __syncwarp();

        // ---- transmittance scan + composite (thread = sample tid) ----
        const float sigma = __expf(ldsf(base + SIGO + 4 * tid));
        const float sd = sigma * delta * dnorm;
        float x = sd;
        #pragma unroll
        for (int off = 1; off < 32; off <<= 1) {
            float v = __shfl_up_sync(0xffffffffu, x, off);
            if (lane >= off) x += v;
        }
        if (lane == 31) stsf(base + SCANW + 4 * wid, x);
        __syncthreads();
        float pre = 0.0f;
        #pragma unroll
        for (int w = 0; w < 4; ++w) if (w < wid) pre += ldsf(base + SCANW + 4 * w);
        const float excl = (x + pre) - sd;
        const float trans = __expf(-excl);
        const float alpha = 1.0f - __expf(-sd);
        const float wgt = trans * alpha * act;

        const float rC = 1.0f / (1.0f + __expf(-(ldsf(base + RGBO + tid * 16)     + p1)));
        const float gC = 1.0f / (1.0f + __expf(-(ldsf(base + RGBO + tid * 16 + 4) + p2)));
        const float bC = 1.0f / (1.0f + __expf(-(ldsf(base + RGBO + tid * 16 + 8) + p3)));

        float cr = wgt * rC, cg = wgt * gC, cb = wgt * bC, ca = wgt;
        #pragma unroll
        for (int off = 16; off > 0; off >>= 1) {
            cr += __shfl_xor_sync(0xffffffffu, cr, off);
            cg += __shfl_xor_sync(0xffffffffu, cg, off);
            cb += __shfl_xor_sync(0xffffffffu, cb, off);
            ca += __shfl_xor_sync(0xffffffffu, ca, off);
        }
        if (lane == 0) {
            stsf(base + PARTO + (wid * 4 + 0) * 4, cr);
            stsf(base + PARTO + (wid * 4 + 1) * 4, cg);
            stsf(base + PARTO + (wid * 4 + 2) * 4, cb);
            stsf(base + PARTO + (wid * 4 + 3) * 4, ca);
        }
        __syncthreads();
        if (tid == 0) {
            float4 o4 = make_float4(0.f, 0.f, 0.f, 0.f);
            #pragma unroll
            for (int w = 0; w < 4; ++w) {
                o4.x += ldsf(base + PARTO + (w * 4 + 0) * 4);
                o4.y += ldsf(base + PARTO + (w * 4 + 1) * 4);
                o4.z += ldsf(base + PARTO + (w * 4 + 2) * 4);
                o4.w += ldsf(base + PARTO + (w * 4 + 3) * 4);
            }
            *(float4*)(out + ray * 4) = o4;
        }
        __syncthreads();
    }
}

extern "C" void kernel_launch(void* const* d_in, const int* in_sizes, int n_in,
                              void* d_out, int out_size) {
    const float* rays_o = (const float*)d_in[0];
    const float* rays_d = (const float*)d_in[1];
    const float* tnoise = (const float*)d_in[2];
    const float* aabb   = (const float*)d_in[3];
    const float* W1     = (const float*)d_in[4];
    const float* b1     = (const float*)d_in[5];
    const float* W2     = (const float*)d_in[6];
    const float* b2     = (const float*)d_in[7];
    const float* Wc1    = (const float*)d_in[8];
    const float* bc1    = (const float*)d_in[9];
    const float* Wc2    = (const float*)d_in[10];
    const float* bc2    = (const float*)d_in[11];
    float* out = (float*)d_out;

    k_setup<<<8, 256>>>(W1, W2, Wc1, Wc2, bc2);
    cudaFuncSetAttribute(nerf_mma2_kernel, cudaFuncAttributeMaxDynamicSharedMemorySize, SMEM_DYN);
    nerf_mma2_kernel<<<NBLK, 128, SMEM_DYN>>>(rays_o, rays_d, tnoise, aabb,
                                              b1, b2, bc1, out);
}

// round 10
// speedup vs baseline: 1.8460x; 1.7540x over previous
#include <cuda_runtime.h>
#include <cuda_bf16.h>
#include <cstdint>

#define N_RAYS_C 16384
#define RAYS_PER_BLK 2
#define NBLK (N_RAYS_C / RAYS_PER_BLK)

// ---- smem byte offsets ----
#define A32HI 0
#define A32LO 10240
#define BOFF  20480
#define B1HI  (BOFF + 0)
#define B1LO  (BOFF + 5120)
#define B2HI  (BOFF + 10240)
#define B2LO  (BOFF + 12544)
#define B3HI  (BOFF + 14848)
#define B3LO  (BOFF + 19968)
#define B4HI  (BOFF + 25088)
#define B4LO  (BOFF + 26240)
#define BBYTES 27392
#define BIAS1 (BOFF + BBYTES)     // 47872, 64 f
#define BIAS2 (BIAS1 + 256)      // 16 f
#define BIAS3 (BIAS2 + 64)       // 64 f
#define SIGO  (BIAS3 + 256)      // 128 f
#define RGBO  (SIGO + 512)       // 128 x 16B
#define SCANW (RGBO + 2048)
#define PARTO (SCANW + 16)
#define SMEM_DYN 51200

#define S32 80
#define S64 144

__device__ __align__(16) unsigned char g_B[BBYTES];
__device__ float g_params[8];   // [1..3] = bc2

// ---- helpers ----
__device__ __forceinline__ uint32_t smem_u32(const void* p) {
    uint32_t a;
    asm("{ .reg .u64 t; cvta.to.shared.u64 t, %1; cvt.u32.u64 %0, t; }" : "=r"(a) : "l"(p));
    return a;
}
__device__ __forceinline__ void sts32(uint32_t a, uint32_t v) {
    asm volatile("st.shared.b32 [%0], %1;" :: "r"(a), "r"(v) : "memory");
}
__device__ __forceinline__ uint32_t lds32(uint32_t a) {
    uint32_t v; asm volatile("ld.shared.b32 %0, [%1];" : "=r"(v) : "r"(a)); return v;
}
__device__ __forceinline__ float ldsf(uint32_t a) { return __uint_as_float(lds32(a)); }
__device__ __forceinline__ void stsf(uint32_t a, float v) { sts32(a, __float_as_uint(v)); }

__device__ __forceinline__ void ldm_x4(uint32_t addr, uint32_t* r) {
    asm volatile("ldmatrix.sync.aligned.m8n8.x4.shared.b16 {%0,%1,%2,%3}, [%4];"
        : "=r"(r[0]), "=r"(r[1]), "=r"(r[2]), "=r"(r[3]) : "r"(addr));
}
__device__ __forceinline__ void ldm_x2(uint32_t addr, uint32_t* r) {
    asm volatile("ldmatrix.sync.aligned.m8n8.x2.shared.b16 {%0,%1}, [%2];"
        : "=r"(r[0]), "=r"(r[1]) : "r"(addr));
}

// pack f32 pair -> bf16x2 hi + residual lo (lower half = first element)
__device__ __forceinline__ void split2(float v0, float v1, uint32_t& hi, uint32_t& lo) {
    asm("cvt.rn.bf16x2.f32 %0, %1, %2;" : "=r"(hi) : "f"(v1), "f"(v0));
    const float h0 = __bfloat162float(__float2bfloat16(v0));
    const float h1 = __bfloat162float(__float2bfloat16(v1));
    const float r0 = v0 - h0, r1 = v1 - h1;
    asm("cvt.rn.bf16x2.f32 %0, %1, %2;" : "=r"(lo) : "f"(r1), "f"(r0));
}

// posenc hi/lo pair -> smem
__device__ __forceinline__ void st_pair(uint32_t hiB, uint32_t loB, uint32_t off,
                                        float v0, float v1) {
    uint32_t hp, lp;
    split2(v0, v1, hp, lp);
    sts32(hiB + off, hp);
    sts32(loB + off, lp);
}

__device__ __forceinline__ void mma16816(float* d,
        uint32_t a0, uint32_t a1, uint32_t a2, uint32_t a3,
        uint32_t b0, uint32_t b1) {
    asm volatile("mma.sync.aligned.m16n8k16.row.col.f32.bf16.bf16.f32 "
        "{%0,%1,%2,%3}, {%4,%5,%6,%7}, {%8,%9}, {%0,%1,%2,%3};"
        : "+f"(d[0]), "+f"(d[1]), "+f"(d[2]), "+f"(d[3])
        : "r"(a0), "r"(a1), "r"(a2), "r"(a3), "r"(b0), "r"(b1));
}
#define MMA(acc, a, b0, b1) mma16816(acc, (a)[0], (a)[1], (a)[2], (a)[3], b0, b1)

// ---- setup: build hi/lo weight image in [n][k]-padded layouts ----
__global__ void k_setup(const float* __restrict__ W1, const float* __restrict__ W2,
                        const float* __restrict__ Wc1, const float* __restrict__ Wc2,
                        const float* __restrict__ bc2) {
    const int tid = blockIdx.x * blockDim.x + threadIdx.x;
    if (tid == 0) { g_params[1] = bc2[0]; g_params[2] = bc2[1]; g_params[3] = bc2[2]; }
    const int n1 = 64 * 40, n2 = 16 * 72, n3 = 64 * 40, n4 = 8 * 72;
    for (int i = tid; i < n1 + n2 + n3 + n4; i += blockDim.x * gridDim.x) {
        float v; int hiOff, loOff;
        if (i < n1) {
            int n = i / 40, k = i % 40;
            v = (k < 27) ? W1[k * 64 + n] : 0.0f;
            hiOff = (B1HI - BOFF) + i * 2; loOff = (B1LO - BOFF) + i * 2;
        } else if (i < n1 + n2) {
            int j = i - n1, n = j / 72, k = j % 72;
            v = (k < 64) ? W2[k * 16 + n] : 0.0f;
            hiOff = (B2HI - BOFF) + j * 2; loOff = (B2LO - BOFF) + j * 2;
        } else if (i < n1 + n2 + n3) {
            int j = i - n1 - n2, n = j / 40, k = j % 40;
            v = (k >= 1 && k < 20) ? Wc1[(k - 1) * 64 + n] : 0.0f;
            hiOff = (B3HI - BOFF) + j * 2; loOff = (B3LO - BOFF) + j * 2;
        } else {
            int j = i - n1 - n2 - n3, n = j / 72, k = j % 72;
            v = (n < 3 && k < 64) ? Wc2[k * 3 + n] : 0.0f;
            hiOff = (B4HI - BOFF) + j * 2; loOff = (B4LO - BOFF) + j * 2;
        }
        __nv_bfloat16 hi = __float2bfloat16(v);
        __nv_bfloat16 lo = __float2bfloat16(v - __bfloat162float(hi));
        *(__nv_bfloat16*)(g_B + hiOff) = hi;
        *(__nv_bfloat16*)(g_B + loOff) = lo;
    }
}

// ---- render ----
__global__ void __launch_bounds__(128) nerf_mma3_kernel(
    const float* __restrict__ rays_o, const float* __restrict__ rays_d,
    const float* __restrict__ tnoise, const float* __restrict__ aabb,
    const float* __restrict__ b1, const float* __restrict__ b2,
    const float* __restrict__ bc1, float* __restrict__ out) {
    extern __shared__ __align__(16) unsigned char sm[];
    const uint32_t base = smem_u32(sm);
    const int tid = threadIdx.x, lane = tid & 31, wid = tid >> 5;
    const int g = lane >> 2, tg = lane & 3;
    const int m0 = wid * 32;

    // prologue: weights + biases
    {
        const int4* src = (const int4*)g_B;
        int4* dst = (int4*)(sm + BOFF);
        for (int i = tid; i < BBYTES / 16; i += 128) dst[i] = src[i];
        if (tid < 64) stsf(base + BIAS1 + 4 * tid, b1[tid]);
        if (tid < 16) stsf(base + BIAS2 + 4 * tid, b2[tid]);
        if (tid >= 64) stsf(base + BIAS3 + 4 * (tid - 64), bc1[tid - 64]);
    }
    const float ax0 = aabb[0], ay0 = aabb[1], az0 = aabb[2];
    const float ax1 = aabb[3], ay1 = aabb[4], az1 = aabb[5];
    const float p1 = g_params[1], p2 = g_params[2], p3 = g_params[3];
    __syncthreads();

    // per-lane ldmatrix address components
    const uint32_t arow = (uint32_t)((lane & 7) + ((lane >> 3) & 1) * 8);
    const uint32_t ak   = (uint32_t)(((lane >> 4) & 1) * 16);
    const uint32_t bn32 = (uint32_t)(((lane & 7) + ((lane >> 4) & 1) * 8) * S32
                                     + ((lane >> 3) & 1) * 16);
    const uint32_t bn64 = (uint32_t)(((lane & 7) + ((lane >> 4) & 1) * 8) * S64
                                     + ((lane >> 3) & 1) * 16);
    const uint32_t bn8  = (uint32_t)((lane & 7) * S64 + ((lane >> 3) & 1) * 16);

    for (int rr = 0; rr < RAYS_PER_BLK; ++rr) {
        const int ray = blockIdx.x * RAYS_PER_BLK + rr;

        // ---- ray setup (thread = sample row tid) ----
        const float ox = rays_o[3 * ray], oy = rays_o[3 * ray + 1], oz = rays_o[3 * ray + 2];
        const float dx = rays_d[3 * ray], dy = rays_d[3 * ray + 1], dz = rays_d[3 * ray + 2];
        const float ix = 1.0f / dx, iy = 1.0f / dy, iz = 1.0f / dz;
        const float t0x = (ax0 - ox) * ix, t1x = (ax1 - ox) * ix;
        const float t0y = (ay0 - oy) * iy, t1y = (ay1 - oy) * iy;
        const float t0z = (az0 - oz) * iz, t1z = (az1 - oz) * iz;
        float tn = fmaxf(fmaxf(fminf(t0x, t1x), fminf(t0y, t1y)), fminf(t0z, t1z));
        tn = fmaxf(tn, 0.0f);
        float tf = fminf(fminf(fmaxf(t0x, t1x), fmaxf(t0y, t1y)), fmaxf(t0z, t1z));
        float act;
        if (tf > tn) { act = 1.0f; } else { act = 0.0f; tn = 0.0f; tf = 0.0f; }
        const float span = tf - tn;
        const float dnorm = sqrtf(dx * dx + dy * dy + dz * dz);

        const float n0 = tnoise[tid * N_RAYS_C + ray];
        const float n1 = (tid < 127) ? tnoise[(tid + 1) * N_RAYS_C + ray] : 0.0f;
        const float ts  = tn + span * (((float)tid + n0) * (1.0f / 128.0f));
        const float ts1 = tn + span * (((float)tid + 1.0f + n1) * (1.0f / 128.0f));
        const float delta = (tid < 127) ? (ts1 - ts) : (tf * 10.0f - ts);

        const float idn = 1.0f / dnorm;
        const float c1 = 0.4886025119029199f;
        const float y0 = 0.28209479177387814f, y1 = c1 * dy * idn;
        const float y2 = c1 * dz * idn,        y3 = c1 * dx * idn;

        {   // posenc -> A32 row tid
            float e[28];
            const float px = ox + ts * dx, py = oy + ts * dy, pz = oz + ts * dz;
            const float xnx = 2.0f * (px - ax0) / (ax1 - ax0) - 1.0f;
            const float xny = 2.0f * (py - ay0) / (ay1 - ay0) - 1.0f;
            const float xnz = 2.0f * (pz - az0) / (az1 - az0) - 1.0f;
            e[0] = xnx; e[1] = xny; e[2] = xnz;
            float f = 3.14159265358979323846f;
            #pragma unroll
            for (int k = 0; k < 4; ++k) {
                float sx, cx, sy, cy, sz, cz;
                __sincosf(f * xnx, &sx, &cx);
                __sincosf(f * xny, &sy, &cy);
                __sincosf(f * xnz, &sz, &cz);
                e[3 + 6 * k + 0] = sx; e[3 + 6 * k + 1] = sy; e[3 + 6 * k + 2] = sz;
                e[6 + 6 * k + 0] = cx; e[6 + 6 * k + 1] = cy; e[6 + 6 * k + 2] = cz;
                f *= 2.0f;
            }
            e[27] = 0.0f;
            const uint32_t rb = (uint32_t)tid * S32;
            #pragma unroll
            for (int p = 0; p < 14; ++p)
                st_pair(base + A32HI, base + A32LO, rb + 4 * p, e[2 * p], e[2 * p + 1]);
            sts32(base + A32HI + rb + 56, 0u); sts32(base + A32HI + rb + 60, 0u);
            sts32(base + A32LO + rb + 56, 0u); sts32(base + A32LO + rb + 60, 0u);
        }
        __syncwarp();

        float acc[2][8][4];
        // ---- stage 1: posenc @ W1 (K32,N64) ----
        {
            uint32_t a1h[2][2][4], a1l[2][2][4];
            #pragma unroll
            for (int mt = 0; mt < 2; ++mt) {
                const uint32_t ao = (uint32_t)((m0 + 16 * mt) * S32) + arow * S32 + ak;
                #pragma unroll
                for (int kb = 0; kb < 2; ++kb) {
                    ldm_x4(base + A32HI + ao + kb * 32, a1h[mt][kb]);
                    ldm_x4(base + A32LO + ao + kb * 32, a1l[mt][kb]);
                }
            }
            #pragma unroll
            for (int mt = 0; mt < 2; ++mt)
                #pragma unroll
                for (int nt = 0; nt < 8; ++nt)
                    acc[mt][nt][0] = acc[mt][nt][1] = acc[mt][nt][2] = acc[mt][nt][3] = 0.f;
            #pragma unroll
            for (int np = 0; np < 4; ++np) {
                #pragma unroll
                for (int kb = 0; kb < 2; ++kb) {
                    uint32_t bh[4], bl[4];
                    const uint32_t bo = bn32 + (uint32_t)(np * 16 * S32) + kb * 32;
                    ldm_x4(base + B1HI + bo, bh);
                    #pragma unroll
                    for (int mt = 0; mt < 2; ++mt) {
                        MMA(acc[mt][2 * np],     a1h[mt][kb], bh[0], bh[1]);
                        MMA(acc[mt][2 * np + 1], a1h[mt][kb], bh[2], bh[3]);
                        MMA(acc[mt][2 * np],     a1l[mt][kb], bh[0], bh[1]);
                        MMA(acc[mt][2 * np + 1], a1l[mt][kb], bh[2], bh[3]);
                    }
                    ldm_x4(base + B1LO + bo, bl);
                    #pragma unroll
                    for (int mt = 0; mt < 2; ++mt) {
                        MMA(acc[mt][2 * np],     a1h[mt][kb], bl[0], bl[1]);
                        MMA(acc[mt][2 * np + 1], a1h[mt][kb], bl[2], bl[3]);
                    }
                }
            }
        }

        // ---- epilogue 1: bias+relu -> stage2 A frags (registers) ----
        uint32_t f2h[2][4][4], f2l[2][4][4];
        #pragma unroll
        for (int nt = 0; nt < 8; ++nt) {
            const int c = nt * 8 + tg * 2;
            const float bb0 = ldsf(base + BIAS1 + 4 * c);
            const float bb1 = ldsf(base + BIAS1 + 4 * c + 4);
            const int kb = nt >> 1, hb = (nt & 1) * 2;
            #pragma unroll
            for (int mt = 0; mt < 2; ++mt) {
                float* d = acc[mt][nt];
                split2(fmaxf(d[0] + bb0, 0.f), fmaxf(d[1] + bb1, 0.f),
                       f2h[mt][kb][hb], f2l[mt][kb][hb]);
                split2(fmaxf(d[2] + bb0, 0.f), fmaxf(d[3] + bb1, 0.f),
                       f2h[mt][kb][hb + 1], f2l[mt][kb][hb + 1]);
            }
        }

        // ---- stage 2: h @ W2 (K64,N16) ----
        #pragma unroll
        for (int mt = 0; mt < 2; ++mt)
            #pragma unroll
            for (int nt = 0; nt < 2; ++nt)
                acc[mt][nt][0] = acc[mt][nt][1] = acc[mt][nt][2] = acc[mt][nt][3] = 0.f;
        #pragma unroll
        for (int kb = 0; kb < 4; ++kb) {
            uint32_t bh[4], bl[4];
            ldm_x4(base + B2HI + bn64 + kb * 32, bh);
            #pragma unroll
            for (int mt = 0; mt < 2; ++mt) {
                MMA(acc[mt][0], f2h[mt][kb], bh[0], bh[1]);
                MMA(acc[mt][1], f2h[mt][kb], bh[2], bh[3]);
                MMA(acc[mt][0], f2l[mt][kb], bh[0], bh[1]);
                MMA(acc[mt][1], f2l[mt][kb], bh[2], bh[3]);
            }
            ldm_x4(base + B2LO + bn64 + kb * 32, bl);
            #pragma unroll
            for (int mt = 0; mt < 2; ++mt) {
                MMA(acc[mt][0], f2h[mt][kb], bl[0], bl[1]);
                MMA(acc[mt][1], f2h[mt][kb], bl[2], bl[3]);
            }
        }

        // ---- epilogue 2: sigma + stage3 A frags (registers) ----
        uint32_t a3h[2][2][4], a3l[2][2][4];
        #pragma unroll
        for (int nt = 0; nt < 2; ++nt) {
            const int c = nt * 8 + tg * 2;
            const float bb0 = ldsf(base + BIAS2 + 4 * c);
            const float bb1 = ldsf(base + BIAS2 + 4 * c + 4);
            const int hb = nt * 2;
            #pragma unroll
            for (int mt = 0; mt < 2; ++mt) {
                float* d = acc[mt][nt];
                const float v0 = d[0] + bb0, v1 = d[1] + bb1;
                const float v2 = d[2] + bb0, v3 = d[3] + bb1;
                split2(v0, v1, a3h[mt][0][hb], a3l[mt][0][hb]);
                split2(v2, v3, a3h[mt][0][hb + 1], a3l[mt][0][hb + 1]);
                if (nt == 0 && tg == 0) {
                    stsf(base + SIGO + 4 * (m0 + 16 * mt + g), v0);
                    stsf(base + SIGO + 4 * (m0 + 16 * mt + g + 8), v2);
                }
            }
        }
        {   // k-block 1: ynm cols 16..19, zeros 20..31
            uint32_t yh = 0u, yl = 0u;
            if (tg == 0)      split2(y0, y1, yh, yl);
            else if (tg == 1) split2(y2, y3, yh, yl);
            #pragma unroll
            for (int mt = 0; mt < 2; ++mt) {
                a3h[mt][1][0] = yh; a3h[mt][1][1] = yh;
                a3h[mt][1][2] = 0u; a3h[mt][1][3] = 0u;
                a3l[mt][1][0] = yl; a3l[mt][1][1] = yl;
                a3l[mt][1][2] = 0u; a3l[mt][1][3] = 0u;
            }
        }

        // ---- stage 3: in2 @ Wc1 (K32,N64) ----
        #pragma unroll
        for (int mt = 0; mt < 2; ++mt)
            #pragma unroll
            for (int nt = 0; nt < 8; ++nt)
                acc[mt][nt][0] = acc[mt][nt][1] = acc[mt][nt][2] = acc[mt][nt][3] = 0.f;
        #pragma unroll
        for (int np = 0; np < 4; ++np) {
            #pragma unroll
            for (int kb = 0; kb < 2; ++kb) {
                uint32_t bh[4], bl[4];
                const uint32_t bo = bn32 + (uint32_t)(np * 16 * S32) + kb * 32;
                ldm_x4(base + B3HI + bo, bh);
                #pragma unroll
                for (int mt = 0; mt < 2; ++mt) {
                    MMA(acc[mt][2 * np],     a3h[mt][kb], bh[0], bh[1]);
                    MMA(acc[mt][2 * np + 1], a3h[mt][kb], bh[2], bh[3]);
                    MMA(acc[mt][2 * np],     a3l[mt][kb], bh[0], bh[1]);
                    MMA(acc[mt][2 * np + 1], a3l[mt][kb], bh[2], bh[3]);
                }
                ldm_x4(base + B3LO + bo, bl);
                #pragma unroll
                for (int mt = 0; mt < 2; ++mt) {
                    MMA(acc[mt][2 * np],     a3h[mt][kb], bl[0], bl[1]);
                    MMA(acc[mt][2 * np + 1], a3h[mt][kb], bl[2], bl[3]);
                }
            }
        }

        // ---- epilogue 3: bias+relu -> stage4 A frags (reuse f2) ----
        #pragma unroll
        for (int nt = 0; nt < 8; ++nt) {
            const int c = nt * 8 + tg * 2;
            const float bb0 = ldsf(base + BIAS3 + 4 * c);
            const float bb1 = ldsf(base + BIAS3 + 4 * c + 4);
            const int kb = nt >> 1, hb = (nt & 1) * 2;
            #pragma unroll
            for (int mt = 0; mt < 2; ++mt) {
                float* d = acc[mt][nt];
                split2(fmaxf(d[0] + bb0, 0.f), fmaxf(d[1] + bb1, 0.f),
                       f2h[mt][kb][hb], f2l[mt][kb][hb]);
                split2(fmaxf(d[2] + bb0, 0.f), fmaxf(d[3] + bb1, 0.f),
                       f2h[mt][kb][hb + 1], f2l[mt][kb][hb + 1]);
            }
        }

        // ---- stage 4: hc @ Wc2 (K64,N8) ----
        float a4[2][4];
        a4[0][0] = a4[0][1] = a4[0][2] = a4[0][3] = 0.f;
        a4[1][0] = a4[1][1] = a4[1][2] = a4[1][3] = 0.f;
        #pragma unroll
        for (int kb = 0; kb < 4; ++kb) {
            uint32_t bh[2], bl[2];
            ldm_x2(base + B4HI + bn8 + kb * 32, bh);
            #pragma unroll
            for (int mt = 0; mt < 2; ++mt) {
                MMA(a4[mt], f2h[mt][kb], bh[0], bh[1]);
                MMA(a4[mt], f2l[mt][kb], bh[0], bh[1]);
            }
            ldm_x2(base + B4LO + bn8 + kb * 32, bl);
            #pragma unroll
            for (int mt = 0; mt < 2; ++mt)
                MMA(a4[mt], f2h[mt][kb], bl[0], bl[1]);
        }
        if (tg < 2) {
            #pragma unroll
            for (int mt = 0; mt < 2; ++mt) {
                const int rA = m0 + 16 * mt + g, rB = rA + 8;
                stsf(base + RGBO + rA * 16 + tg * 8,     a4[mt][0]);
                stsf(base + RGBO + rA * 16 + tg * 8 + 4, a4[mt][1]);
                stsf(base + RGBO + rB * 16 + tg * 8,     a4[mt][2]);
                stsf(base + RGBO + rB * 16 + tg * 8 + 4, a4[mt][3]);
            }
        }
        __syncthreads();

        // ---- transmittance scan + composite (thread = sample tid) ----
        const float sigma = __expf(ldsf(base + SIGO + 4 * tid));
        const float sd = sigma * delta * dnorm;
        float x = sd;
        #pragma unroll
        for (int off = 1; off < 32; off <<= 1) {
            float v = __shfl_up_sync(0xffffffffu, x, off);
            if (lane >= off) x += v;
        }
        if (lane == 31) stsf(base + SCANW + 4 * wid, x);
        __syncthreads();
        float pre = 0.0f;
        #pragma unroll
        for (int w = 0; w < 4; ++w) if (w < wid) pre += ldsf(base + SCANW + 4 * w);
        const float excl = (x + pre) - sd;
        const float trans = __expf(-excl);
        const float alpha = 1.0f - __expf(-sd);
        const float wgt = trans * alpha * act;

        const float rC = 1.0f / (1.0f + __expf(-(ldsf(base + RGBO + tid * 16)     + p1)));
        const float gC = 1.0f / (1.0f + __expf(-(ldsf(base + RGBO + tid * 16 + 4) + p2)));
        const float bC = 1.0f / (1.0f + __expf(-(ldsf(base + RGBO + tid * 16 + 8) + p3)));

        float cr = wgt * rC, cg = wgt * gC, cb = wgt * bC, ca = wgt;
        #pragma unroll
        for (int off = 16; off > 0; off >>= 1) {
            cr += __shfl_xor_sync(0xffffffffu, cr, off);
            cg += __shfl_xor_sync(0xffffffffu, cg, off);
            cb += __shfl_xor_sync(0xffffffffu, cb, off);
            ca += __shfl_xor_sync(0xffffffffu, ca, off);
        }
        if (lane == 0) {
            stsf(base + PARTO + (wid * 4 + 0) * 4, cr);
            stsf(base + PARTO + (wid * 4 + 1) * 4, cg);
            stsf(base + PARTO + (wid * 4 + 2) * 4, cb);
            stsf(base + PARTO + (wid * 4 + 3) * 4, ca);
        }
        __syncthreads();
        if (tid == 0) {
            float4 o4 = make_float4(0.f, 0.f, 0.f, 0.f);
            #pragma unroll
            for (int w = 0; w < 4; ++w) {
                o4.x += ldsf(base + PARTO + (w * 4 + 0) * 4);
                o4.y += ldsf(base + PARTO + (w * 4 + 1) * 4);
                o4.z += ldsf(base + PARTO + (w * 4 + 2) * 4);
                o4.w += ldsf(base + PARTO + (w * 4 + 3) * 4);
            }
            *(float4*)(out + ray * 4) = o4;
        }
        __syncthreads();
    }
}

extern "C" void kernel_launch(void* const* d_in, const int* in_sizes, int n_in,
                              void* d_out, int out_size) {
    const float* rays_o = (const float*)d_in[0];
    const float* rays_d = (const float*)d_in[1];
    const float* tnoise = (const float*)d_in[2];
    const float* aabb   = (const float*)d_in[3];
    const float* W1     = (const float*)d_in[4];
    const float* b1     = (const float*)d_in[5];
    const float* W2     = (const float*)d_in[6];
    const float* b2     = (const float*)d_in[7];
    const float* Wc1    = (const float*)d_in[8];
    const float* bc1    = (const float*)d_in[9];
    const float* Wc2    = (const float*)d_in[10];
    const float* bc2    = (const float*)d_in[11];
    float* out = (float*)d_out;

    k_setup<<<8, 256>>>(W1, W2, Wc1, Wc2, bc2);
    cudaFuncSetAttribute(nerf_mma3_kernel, cudaFuncAttributeMaxDynamicSharedMemorySize, SMEM_DYN);
    nerf_mma3_kernel<<<NBLK, 128, SMEM_DYN>>>(rays_o, rays_d, tnoise, aabb,
                                              b1, b2, bc1, out);
}

// round 11
// speedup vs baseline: 2.3281x; 1.2612x over previous
#include <cuda_runtime.h>
#include <cuda_bf16.h>
#include <cstdint>

#define N_RAYS_C 16384
#define RAYS_PER_BLK 2
#define NBLK (N_RAYS_C / RAYS_PER_BLK)

// ---- smem byte offsets ----
#define A32HI 0
#define A32LO 10240
#define BOFF  20480
#define B1HI  (BOFF + 0)
#define B1LO  (BOFF + 5120)
#define B2HI  (BOFF + 10240)
#define B2LO  (BOFF + 12544)
#define B3HI  (BOFF + 14848)
#define B3LO  (BOFF + 19968)
#define B4HI  (BOFF + 25088)
#define B4LO  (BOFF + 26240)
#define BBYTES 27392
#define BIAS1 (BOFF + BBYTES)     // 64 f
#define BIAS2 (BIAS1 + 256)      // 16 f
#define BIAS3 (BIAS2 + 64)       // 64 f (per-ray fused bias)
#define SIGO  (BIAS3 + 256)      // 128 f
#define RGBO  (SIGO + 512)       // 128 x 16B
#define SCANW (RGBO + 2048)
#define PARTO (SCANW + 16)
#define SMEM_DYN 51200

#define S32 80
#define S64 144

__device__ __align__(16) unsigned char g_B[BBYTES];
__device__ float g_params[8];   // [1..3] = bc2

// ---- helpers ----
__device__ __forceinline__ uint32_t smem_u32(const void* p) {
    uint32_t a;
    asm("{ .reg .u64 t; cvta.to.shared.u64 t, %1; cvt.u32.u64 %0, t; }" : "=r"(a) : "l"(p));
    return a;
}
__device__ __forceinline__ void sts32(uint32_t a, uint32_t v) {
    asm volatile("st.shared.b32 [%0], %1;" :: "r"(a), "r"(v) : "memory");
}
__device__ __forceinline__ uint32_t lds32(uint32_t a) {
    uint32_t v; asm volatile("ld.shared.b32 %0, [%1];" : "=r"(v) : "r"(a)); return v;
}
__device__ __forceinline__ float ldsf(uint32_t a) { return __uint_as_float(lds32(a)); }
__device__ __forceinline__ void stsf(uint32_t a, float v) { sts32(a, __float_as_uint(v)); }

__device__ __forceinline__ void ldm_x4(uint32_t addr, uint32_t* r) {
    asm volatile("ldmatrix.sync.aligned.m8n8.x4.shared.b16 {%0,%1,%2,%3}, [%4];"
        : "=r"(r[0]), "=r"(r[1]), "=r"(r[2]), "=r"(r[3]) : "r"(addr));
}
__device__ __forceinline__ void ldm_x2(uint32_t addr, uint32_t* r) {
    asm volatile("ldmatrix.sync.aligned.m8n8.x2.shared.b16 {%0,%1}, [%2];"
        : "=r"(r[0]), "=r"(r[1]) : "r"(addr));
}

// pack f32 pair -> bf16x2 hi + residual lo; residual via bit-extract of hi (no extra cvts)
__device__ __forceinline__ void split2(float v0, float v1, uint32_t& hi, uint32_t& lo) {
    asm("cvt.rn.bf16x2.f32 %0, %1, %2;" : "=r"(hi) : "f"(v1), "f"(v0));
    const float r0 = v0 - __uint_as_float(hi << 16);
    const float r1 = v1 - __uint_as_float(hi & 0xffff0000u);
    asm("cvt.rn.bf16x2.f32 %0, %1, %2;" : "=r"(lo) : "f"(r1), "f"(r0));
}

// posenc hi/lo pair -> smem
__device__ __forceinline__ void st_pair(uint32_t hiB, uint32_t loB, uint32_t off,
                                        float v0, float v1) {
    uint32_t hp, lp;
    split2(v0, v1, hp, lp);
    sts32(hiB + off, hp);
    sts32(loB + off, lp);
}

__device__ __forceinline__ void mma16816(float* d,
        uint32_t a0, uint32_t a1, uint32_t a2, uint32_t a3,
        uint32_t b0, uint32_t b1) {
    asm volatile("mma.sync.aligned.m16n8k16.row.col.f32.bf16.bf16.f32 "
        "{%0,%1,%2,%3}, {%4,%5,%6,%7}, {%8,%9}, {%0,%1,%2,%3};"
        : "+f"(d[0]), "+f"(d[1]), "+f"(d[2]), "+f"(d[3])
        : "r"(a0), "r"(a1), "r"(a2), "r"(a3), "r"(b0), "r"(b1));
}
#define MMA(acc, a, b0, b1) mma16816(acc, (a)[0], (a)[1], (a)[2], (a)[3], b0, b1)

// ---- setup: build hi/lo weight image in [n][k]-padded layouts ----
__global__ void k_setup(const float* __restrict__ W1, const float* __restrict__ W2,
                        const float* __restrict__ Wc1, const float* __restrict__ Wc2,
                        const float* __restrict__ bc2) {
    const int tid = blockIdx.x * blockDim.x + threadIdx.x;
    if (tid == 0) { g_params[1] = bc2[0]; g_params[2] = bc2[1]; g_params[3] = bc2[2]; }
    const int n1 = 64 * 40, n2 = 16 * 72, n3 = 64 * 40, n4 = 8 * 72;
    for (int i = tid; i < n1 + n2 + n3 + n4; i += blockDim.x * gridDim.x) {
        float v; int hiOff, loOff;
        if (i < n1) {
            int n = i / 40, k = i % 40;
            v = (k < 27) ? W1[k * 64 + n] : 0.0f;
            hiOff = (B1HI - BOFF) + i * 2; loOff = (B1LO - BOFF) + i * 2;
        } else if (i < n1 + n2) {
            int j = i - n1, n = j / 72, k = j % 72;
            v = (k < 64) ? W2[k * 16 + n] : 0.0f;
            hiOff = (B2HI - BOFF) + j * 2; loOff = (B2LO - BOFF) + j * 2;
        } else if (i < n1 + n2 + n3) {
            int j = i - n1 - n2, n = j / 40, k = j % 40;
            v = (k >= 1 && k < 16) ? Wc1[(k - 1) * 64 + n] : 0.0f;   // feat rows only; ynm folded into bias
            hiOff = (B3HI - BOFF) + j * 2; loOff = (B3LO - BOFF) + j * 2;
        } else {
            int j = i - n1 - n2 - n3, n = j / 72, k = j % 72;
            v = (n < 3 && k < 64) ? Wc2[k * 3 + n] : 0.0f;
            hiOff = (B4HI - BOFF) + j * 2; loOff = (B4LO - BOFF) + j * 2;
        }
        __nv_bfloat16 hi = __float2bfloat16(v);
        __nv_bfloat16 lo = __float2bfloat16(v - __bfloat162float(hi));
        *(__nv_bfloat16*)(g_B + hiOff) = hi;
        *(__nv_bfloat16*)(g_B + loOff) = lo;
    }
}

// ---- render ----
__global__ void __launch_bounds__(128, 4) nerf_mma4_kernel(
    const float* __restrict__ rays_o, const float* __restrict__ rays_d,
    const float* __restrict__ tnoise, const float* __restrict__ aabb,
    const float* __restrict__ b1, const float* __restrict__ b2,
    const float* __restrict__ bc1, const float* __restrict__ Wc1,
    float* __restrict__ out) {
    extern __shared__ __align__(16) unsigned char sm[];
    const uint32_t base = smem_u32(sm);
    const int tid = threadIdx.x, lane = tid & 31, wid = tid >> 5;
    const int g = lane >> 2, tg = lane & 3;
    const int m0 = wid * 32;

    // prologue: weights + biases
    {
        const int4* src = (const int4*)g_B;
        int4* dst = (int4*)(sm + BOFF);
        for (int i = tid; i < BBYTES / 16; i += 128) dst[i] = src[i];
        if (tid < 64) stsf(base + BIAS1 + 4 * tid, b1[tid]);
        if (tid < 16) stsf(base + BIAS2 + 4 * tid, b2[tid]);
    }
    const float ax0 = aabb[0], ay0 = aabb[1], az0 = aabb[2];
    const float ax1 = aabb[3], ay1 = aabb[4], az1 = aabb[5];
    const float p1 = g_params[1], p2 = g_params[2], p3 = g_params[3];
    __syncthreads();

    // per-lane ldmatrix address components
    const uint32_t arow = (uint32_t)((lane & 7) + ((lane >> 3) & 1) * 8);
    const uint32_t ak   = (uint32_t)(((lane >> 4) & 1) * 16);
    const uint32_t bn32 = (uint32_t)(((lane & 7) + ((lane >> 4) & 1) * 8) * S32
                                     + ((lane >> 3) & 1) * 16);
    const uint32_t bn64 = (uint32_t)(((lane & 7) + ((lane >> 4) & 1) * 8) * S64
                                     + ((lane >> 3) & 1) * 16);
    const uint32_t bn8  = (uint32_t)((lane & 7) * S64 + ((lane >> 3) & 1) * 16);

    for (int rr = 0; rr < RAYS_PER_BLK; ++rr) {
        const int ray = blockIdx.x * RAYS_PER_BLK + rr;

        // ---- ray setup (thread = sample row tid) ----
        const float ox = rays_o[3 * ray], oy = rays_o[3 * ray + 1], oz = rays_o[3 * ray + 2];
        const float dx = rays_d[3 * ray], dy = rays_d[3 * ray + 1], dz = rays_d[3 * ray + 2];
        const float ix = 1.0f / dx, iy = 1.0f / dy, iz = 1.0f / dz;
        const float t0x = (ax0 - ox) * ix, t1x = (ax1 - ox) * ix;
        const float t0y = (ay0 - oy) * iy, t1y = (ay1 - oy) * iy;
        const float t0z = (az0 - oz) * iz, t1z = (az1 - oz) * iz;
        float tn = fmaxf(fmaxf(fminf(t0x, t1x), fminf(t0y, t1y)), fminf(t0z, t1z));
        tn = fmaxf(tn, 0.0f);
        float tf = fminf(fminf(fmaxf(t0x, t1x), fmaxf(t0y, t1y)), fmaxf(t0z, t1z));
        float act;
        if (tf > tn) { act = 1.0f; } else { act = 0.0f; tn = 0.0f; tf = 0.0f; }
        const float span = tf - tn;
        const float dnorm = sqrtf(dx * dx + dy * dy + dz * dz);

        const float n0 = tnoise[tid * N_RAYS_C + ray];
        const float n1 = (tid < 127) ? tnoise[(tid + 1) * N_RAYS_C + ray] : 0.0f;
        const float ts  = tn + span * (((float)tid + n0) * (1.0f / 128.0f));
        const float ts1 = tn + span * (((float)tid + 1.0f + n1) * (1.0f / 128.0f));
        const float delta = (tid < 127) ? (ts1 - ts) : (tf * 10.0f - ts);

        const float idn = 1.0f / dnorm;
        const float c1 = 0.4886025119029199f;
        const float y0 = 0.28209479177387814f, y1 = c1 * dy * idn;
        const float y2 = c1 * dz * idn,        y3 = c1 * dx * idn;

        // per-ray fused color-layer bias: bc1 + ynm @ Wc1[15:19]  (fp32, exact)
        if (tid < 64) {
            const float s = bc1[tid]
                          + y0 * Wc1[15 * 64 + tid] + y1 * Wc1[16 * 64 + tid]
                          + y2 * Wc1[17 * 64 + tid] + y3 * Wc1[18 * 64 + tid];
            stsf(base + BIAS3 + 4 * tid, s);
        }

        {   // posenc -> A32 row tid
            float e[28];
            const float px = ox + ts * dx, py = oy + ts * dy, pz = oz + ts * dz;
            const float xnx = 2.0f * (px - ax0) / (ax1 - ax0) - 1.0f;
            const float xny = 2.0f * (py - ay0) / (ay1 - ay0) - 1.0f;
            const float xnz = 2.0f * (pz - az0) / (az1 - az0) - 1.0f;
            e[0] = xnx; e[1] = xny; e[2] = xnz;
            float f = 3.14159265358979323846f;
            #pragma unroll
            for (int k = 0; k < 4; ++k) {
                float sx, cx, sy, cy, sz, cz;
                __sincosf(f * xnx, &sx, &cx);
                __sincosf(f * xny, &sy, &cy);
                __sincosf(f * xnz, &sz, &cz);
                e[3 + 6 * k + 0] = sx; e[3 + 6 * k + 1] = sy; e[3 + 6 * k + 2] = sz;
                e[6 + 6 * k + 0] = cx; e[6 + 6 * k + 1] = cy; e[6 + 6 * k + 2] = cz;
                f *= 2.0f;
            }
            e[27] = 0.0f;
            const uint32_t rb = (uint32_t)tid * S32;
            #pragma unroll
            for (int p = 0; p < 14; ++p)
                st_pair(base + A32HI, base + A32LO, rb + 4 * p, e[2 * p], e[2 * p + 1]);
            sts32(base + A32HI + rb + 56, 0u); sts32(base + A32HI + rb + 60, 0u);
            sts32(base + A32LO + rb + 56, 0u); sts32(base + A32LO + rb + 60, 0u);
        }
        __syncthreads();   // A32 + BIAS3 visible to all warps

        float acc[2][8][4];
        // ---- stage 1: posenc @ W1 (K32,N64) ----
        {
            uint32_t a1h[2][2][4], a1l[2][2][4];
            #pragma unroll
            for (int mt = 0; mt < 2; ++mt) {
                const uint32_t ao = (uint32_t)((m0 + 16 * mt) * S32) + arow * S32 + ak;
                #pragma unroll
                for (int kb = 0; kb < 2; ++kb) {
                    ldm_x4(base + A32HI + ao + kb * 32, a1h[mt][kb]);
                    ldm_x4(base + A32LO + ao + kb * 32, a1l[mt][kb]);
                }
            }
            #pragma unroll
            for (int mt = 0; mt < 2; ++mt)
                #pragma unroll
                for (int nt = 0; nt < 8; ++nt)
                    acc[mt][nt][0] = acc[mt][nt][1] = acc[mt][nt][2] = acc[mt][nt][3] = 0.f;
            #pragma unroll
            for (int np = 0; np < 4; ++np) {
                #pragma unroll
                for (int kb = 0; kb < 2; ++kb) {
                    uint32_t bh[4], bl[4];
                    const uint32_t bo = bn32 + (uint32_t)(np * 16 * S32) + kb * 32;
                    ldm_x4(base + B1HI + bo, bh);
                    #pragma unroll
                    for (int mt = 0; mt < 2; ++mt) {
                        MMA(acc[mt][2 * np],     a1h[mt][kb], bh[0], bh[1]);
                        MMA(acc[mt][2 * np + 1], a1h[mt][kb], bh[2], bh[3]);
                        MMA(acc[mt][2 * np],     a1l[mt][kb], bh[0], bh[1]);
                        MMA(acc[mt][2 * np + 1], a1l[mt][kb], bh[2], bh[3]);
                    }
                    ldm_x4(base + B1LO + bo, bl);
                    #pragma unroll
                    for (int mt = 0; mt < 2; ++mt) {
                        MMA(acc[mt][2 * np],     a1h[mt][kb], bl[0], bl[1]);
                        MMA(acc[mt][2 * np + 1], a1h[mt][kb], bl[2], bl[3]);
                    }
                }
            }
        }

        // ---- epilogue 1: bias+relu -> stage2 A frags (registers) ----
        uint32_t f2h[2][4][4], f2l[2][4][4];
        #pragma unroll
        for (int nt = 0; nt < 8; ++nt) {
            const int c = nt * 8 + tg * 2;
            const float bb0 = ldsf(base + BIAS1 + 4 * c);
            const float bb1 = ldsf(base + BIAS1 + 4 * c + 4);
            const int kb = nt >> 1, hb = (nt & 1) * 2;
            #pragma unroll
            for (int mt = 0; mt < 2; ++mt) {
                float* d = acc[mt][nt];
                split2(fmaxf(d[0] + bb0, 0.f), fmaxf(d[1] + bb1, 0.f),
                       f2h[mt][kb][hb], f2l[mt][kb][hb]);
                split2(fmaxf(d[2] + bb0, 0.f), fmaxf(d[3] + bb1, 0.f),
                       f2h[mt][kb][hb + 1], f2l[mt][kb][hb + 1]);
            }
        }

        // ---- stage 2: h @ W2 (K64,N16) ----
        #pragma unroll
        for (int mt = 0; mt < 2; ++mt)
            #pragma unroll
            for (int nt = 0; nt < 2; ++nt)
                acc[mt][nt][0] = acc[mt][nt][1] = acc[mt][nt][2] = acc[mt][nt][3] = 0.f;
        #pragma unroll
        for (int kb = 0; kb < 4; ++kb) {
            uint32_t bh[4], bl[4];
            ldm_x4(base + B2HI + bn64 + kb * 32, bh);
            #pragma unroll
            for (int mt = 0; mt < 2; ++mt) {
                MMA(acc[mt][0], f2h[mt][kb], bh[0], bh[1]);
                MMA(acc[mt][1], f2h[mt][kb], bh[2], bh[3]);
                MMA(acc[mt][0], f2l[mt][kb], bh[0], bh[1]);
                MMA(acc[mt][1], f2l[mt][kb], bh[2], bh[3]);
            }
            ldm_x4(base + B2LO + bn64 + kb * 32, bl);
            #pragma unroll
            for (int mt = 0; mt < 2; ++mt) {
                MMA(acc[mt][0], f2h[mt][kb], bl[0], bl[1]);
                MMA(acc[mt][1], f2h[mt][kb], bl[2], bl[3]);
            }
        }

        // ---- epilogue 2: sigma + stage3 A frags (K=16: cols 0..15) ----
        uint32_t a3h[2][4], a3l[2][4];
        #pragma unroll
        for (int nt = 0; nt < 2; ++nt) {
            const int c = nt * 8 + tg * 2;
            const float bb0 = ldsf(base + BIAS2 + 4 * c);
            const float bb1 = ldsf(base + BIAS2 + 4 * c + 4);
            const int hb = nt * 2;
            #pragma unroll
            for (int mt = 0; mt < 2; ++mt) {
                float* d = acc[mt][nt];
                const float v0 = d[0] + bb0, v1 = d[1] + bb1;
                const float v2 = d[2] + bb0, v3 = d[3] + bb1;
                split2(v0, v1, a3h[mt][hb], a3l[mt][hb]);
                split2(v2, v3, a3h[mt][hb + 1], a3l[mt][hb + 1]);
                if (nt == 0 && tg == 0) {
                    stsf(base + SIGO + 4 * (m0 + 16 * mt + g), v0);
                    stsf(base + SIGO + 4 * (m0 + 16 * mt + g + 8), v2);
                }
            }
        }

        // ---- stage 3: feat @ Wc1[0:15] (K16,N64) ----
        #pragma unroll
        for (int mt = 0; mt < 2; ++mt)
            #pragma unroll
            for (int nt = 0; nt < 8; ++nt)
                acc[mt][nt][0] = acc[mt][nt][1] = acc[mt][nt][2] = acc[mt][nt][3] = 0.f;
        #pragma unroll
        for (int np = 0; np < 4; ++np) {
            uint32_t bh[4], bl[4];
            const uint32_t bo = bn32 + (uint32_t)(np * 16 * S32);
            ldm_x4(base + B3HI + bo, bh);
            #pragma unroll
            for (int mt = 0; mt < 2; ++mt) {
                MMA(acc[mt][2 * np],     a3h[mt], bh[0], bh[1]);
                MMA(acc[mt][2 * np + 1], a3h[mt], bh[2], bh[3]);
                MMA(acc[mt][2 * np],     a3l[mt], bh[0], bh[1]);
                MMA(acc[mt][2 * np + 1], a3l[mt], bh[2], bh[3]);
            }
            ldm_x4(base + B3LO + bo, bl);
            #pragma unroll
            for (int mt = 0; mt < 2; ++mt) {
                MMA(acc[mt][2 * np],     a3h[mt], bl[0], bl[1]);
                MMA(acc[mt][2 * np + 1], a3h[mt], bl[2], bl[3]);
            }
        }

        // ---- epilogue 3: (per-ray fused bias)+relu -> stage4 A frags (reuse f2) ----
        #pragma unroll
        for (int nt = 0; nt < 8; ++nt) {
            const int c = nt * 8 + tg * 2;
            const float bb0 = ldsf(base + BIAS3 + 4 * c);
            const float bb1 = ldsf(base + BIAS3 + 4 * c + 4);
            const int kb = nt >> 1, hb = (nt & 1) * 2;
            #pragma unroll
            for (int mt = 0; mt < 2; ++mt) {
                float* d = acc[mt][nt];
                split2(fmaxf(d[0] + bb0, 0.f), fmaxf(d[1] + bb1, 0.f),
                       f2h[mt][kb][hb], f2l[mt][kb][hb]);
                split2(fmaxf(d[2] + bb0, 0.f), fmaxf(d[3] + bb1, 0.f),
                       f2h[mt][kb][hb + 1], f2l[mt][kb][hb + 1]);
            }
        }

        // ---- stage 4: hc @ Wc2 (K64,N8) ----
        float a4[2][4];
        a4[0][0] = a4[0][1] = a4[0][2] = a4[0][3] = 0.f;
        a4[1][0] = a4[1][1] = a4[1][2] = a4[1][3] = 0.f;
        #pragma unroll
        for (int kb = 0; kb < 4; ++kb) {
            uint32_t bh[2], bl[2];
            ldm_x2(base + B4HI + bn8 + kb * 32, bh);
            #pragma unroll
            for (int mt = 0; mt < 2; ++mt) {
                MMA(a4[mt], f2h[mt][kb], bh[0], bh[1]);
                MMA(a4[mt], f2l[mt][kb], bh[0], bh[1]);
            }
            ldm_x2(base + B4LO + bn8 + kb * 32, bl);
            #pragma unroll
            for (int mt = 0; mt < 2; ++mt)
                MMA(a4[mt], f2h[mt][kb], bl[0], bl[1]);
        }
        if (tg < 2) {
            #pragma unroll
            for (int mt = 0; mt < 2; ++mt) {
                const int rA = m0 + 16 * mt + g, rB = rA + 8;
                stsf(base + RGBO + rA * 16 + tg * 8,     a4[mt][0]);
                stsf(base + RGBO + rA * 16 + tg * 8 + 4, a4[mt][1]);
                stsf(base + RGBO + rB * 16 + tg * 8,     a4[mt][2]);
                stsf(base + RGBO + rB * 16 + tg * 8 + 4, a4[mt][3]);
            }
        }
        __syncthreads();

        // ---- transmittance scan + composite (thread = sample tid) ----
        const float sigma = __expf(ldsf(base + SIGO + 4 * tid));
        const float sd = sigma * delta * dnorm;
        float x = sd;
        #pragma unroll
        for (int off = 1; off < 32; off <<= 1) {
            float v = __shfl_up_sync(0xffffffffu, x, off);
            if (lane >= off) x += v;
        }
        if (lane == 31) stsf(base + SCANW + 4 * wid, x);
        __syncthreads();
        float pre = 0.0f;
        #pragma unroll
        for (int w = 0; w < 4; ++w) if (w < wid) pre += ldsf(base + SCANW + 4 * w);
        const float excl = (x + pre) - sd;
        const float trans = __expf(-excl);
        const float alpha = 1.0f - __expf(-sd);
        const float wgt = trans * alpha * act;

        const float rC = 1.0f / (1.0f + __expf(-(ldsf(base + RGBO + tid * 16)     + p1)));
        const float gC = 1.0f / (1.0f + __expf(-(ldsf(base + RGBO + tid * 16 + 4) + p2)));
        const float bC = 1.0f / (1.0f + __expf(-(ldsf(base + RGBO + tid * 16 + 8) + p3)));

        float cr = wgt * rC, cg = wgt * gC, cb = wgt * bC, ca = wgt;
        #pragma unroll
        for (int off = 16; off > 0; off >>= 1) {
            cr += __shfl_xor_sync(0xffffffffu, cr, off);
            cg += __shfl_xor_sync(0xffffffffu, cg, off);
            cb += __shfl_xor_sync(0xffffffffu, cb, off);
            ca += __shfl_xor_sync(0xffffffffu, ca, off);
        }
        if (lane == 0) {
            stsf(base + PARTO + (wid * 4 + 0) * 4, cr);
            stsf(base + PARTO + (wid * 4 + 1) * 4, cg);
            stsf(base + PARTO + (wid * 4 + 2) * 4, cb);
            stsf(base + PARTO + (wid * 4 + 3) * 4, ca);
        }
        __syncthreads();
        if (tid == 0) {
            float4 o4 = make_float4(0.f, 0.f, 0.f, 0.f);
            #pragma unroll
            for (int w = 0; w < 4; ++w) {
                o4.x += ldsf(base + PARTO + (w * 4 + 0) * 4);
                o4.y += ldsf(base + PARTO + (w * 4 + 1) * 4);
                o4.z += ldsf(base + PARTO + (w * 4 + 2) * 4);
                o4.w += ldsf(base + PARTO + (w * 4 + 3) * 4);
            }
            *(float4*)(out + ray * 4) = o4;
        }
        __syncthreads();
    }
}

extern "C" void kernel_launch(void* const* d_in, const int* in_sizes, int n_in,
                              void* d_out, int out_size) {
    const float* rays_o = (const float*)d_in[0];
    const float* rays_d = (const float*)d_in[1];
    const float* tnoise = (const float*)d_in[2];
    const float* aabb   = (const float*)d_in[3];
    const float* W1     = (const float*)d_in[4];
    const float* b1     = (const float*)d_in[5];
    const float* W2     = (const float*)d_in[6];
    const float* b2     = (const float*)d_in[7];
    const float* Wc1    = (const float*)d_in[8];
    const float* bc1    = (const float*)d_in[9];
    const float* Wc2    = (const float*)d_in[10];
    const float* bc2    = (const float*)d_in[11];
    float* out = (float*)d_out;

    k_setup<<<8, 256>>>(W1, W2, Wc1, Wc2, bc2);
    cudaFuncSetAttribute(nerf_mma4_kernel, cudaFuncAttributeMaxDynamicSharedMemorySize, SMEM_DYN);
    nerf_mma4_kernel<<<NBLK, 128, SMEM_DYN>>>(rays_o, rays_d, tnoise, aabb,
                                              b1, b2, bc1, Wc1, out);
}

// round 12
// speedup vs baseline: 2.3757x; 1.0205x over previous
#include <cuda_runtime.h>
#include <cuda_bf16.h>
#include <cstdint>

#define N_RAYS_C 16384
#define RAYS_PER_BLK 2
#define NBLK (N_RAYS_C / RAYS_PER_BLK)

// ---- smem byte offsets ----
#define A32HI 0
#define A32LO 10240
#define BOFF  20480
#define B1HI  (BOFF + 0)
#define B1LO  (BOFF + 5120)
#define B2HI  (BOFF + 10240)
#define B2LO  (BOFF + 12544)
#define B3HI  (BOFF + 14848)
#define B3LO  (BOFF + 19968)
#define B4HI  (BOFF + 25088)
#define B4LO  (BOFF + 26240)
#define BBYTES 27392
#define BIAS1 (BOFF + BBYTES)    // 64 f
#define BIAS2 (BIAS1 + 256)      // 16 f
#define BIAS3 (BIAS2 + 64)       // 64 f (per-ray fused bias)
#define SIGO  (BIAS3 + 256)      // 128 f
#define RGBO  (SIGO + 512)       // 128 x 16B
#define SCANW (RGBO + 2048)
#define PARTO (SCANW + 16)
#define SMEM_DYN 51200

#define S32 80
#define S64 144

__device__ __align__(16) unsigned char g_B[BBYTES];
__device__ float g_params[8];   // [1..3] = bc2

// ---- helpers ----
__device__ __forceinline__ uint32_t smem_u32(const void* p) {
    uint32_t a;
    asm("{ .reg .u64 t; cvta.to.shared.u64 t, %1; cvt.u32.u64 %0, t; }" : "=r"(a) : "l"(p));
    return a;
}
__device__ __forceinline__ void sts32(uint32_t a, uint32_t v) {
    asm volatile("st.shared.b32 [%0], %1;" :: "r"(a), "r"(v) : "memory");
}
__device__ __forceinline__ void sts128(uint32_t a, uint32_t v0, uint32_t v1,
                                       uint32_t v2, uint32_t v3) {
    asm volatile("st.shared.v4.b32 [%0], {%1,%2,%3,%4};"
                 :: "r"(a), "r"(v0), "r"(v1), "r"(v2), "r"(v3) : "memory");
}
__device__ __forceinline__ uint32_t lds32(uint32_t a) {
    uint32_t v; asm volatile("ld.shared.b32 %0, [%1];" : "=r"(v) : "r"(a)); return v;
}
__device__ __forceinline__ float ldsf(uint32_t a) { return __uint_as_float(lds32(a)); }
__device__ __forceinline__ void stsf(uint32_t a, float v) { sts32(a, __float_as_uint(v)); }

__device__ __forceinline__ void ldm_x4(uint32_t addr, uint32_t* r) {
    asm volatile("ldmatrix.sync.aligned.m8n8.x4.shared.b16 {%0,%1,%2,%3}, [%4];"
        : "=r"(r[0]), "=r"(r[1]), "=r"(r[2]), "=r"(r[3]) : "r"(addr));
}
__device__ __forceinline__ void ldm_x2(uint32_t addr, uint32_t* r) {
    asm volatile("ldmatrix.sync.aligned.m8n8.x2.shared.b16 {%0,%1}, [%2];"
        : "=r"(r[0]), "=r"(r[1]) : "r"(addr));
}

// pack f32 pair -> bf16x2 hi + residual lo; residual via bit-extract of hi
__device__ __forceinline__ void split2(float v0, float v1, uint32_t& hi, uint32_t& lo) {
    asm("cvt.rn.bf16x2.f32 %0, %1, %2;" : "=r"(hi) : "f"(v1), "f"(v0));
    const float r0 = v0 - __uint_as_float(hi << 16);
    const float r1 = v1 - __uint_as_float(hi & 0xffff0000u);
    asm("cvt.rn.bf16x2.f32 %0, %1, %2;" : "=r"(lo) : "f"(r1), "f"(r0));
}

__device__ __forceinline__ void mma16816(float* d,
        uint32_t a0, uint32_t a1, uint32_t a2, uint32_t a3,
        uint32_t b0, uint32_t b1) {
    asm volatile("mma.sync.aligned.m16n8k16.row.col.f32.bf16.bf16.f32 "
        "{%0,%1,%2,%3}, {%4,%5,%6,%7}, {%8,%9}, {%0,%1,%2,%3};"
        : "+f"(d[0]), "+f"(d[1]), "+f"(d[2]), "+f"(d[3])
        : "r"(a0), "r"(a1), "r"(a2), "r"(a3), "r"(b0), "r"(b1));
}
#define MMA(acc, a, b0, b1) mma16816(acc, (a)[0], (a)[1], (a)[2], (a)[3], b0, b1)

// ---- setup: build hi/lo weight image in [n][k]-padded layouts ----
__global__ void k_setup(const float* __restrict__ W1, const float* __restrict__ W2,
                        const float* __restrict__ Wc1, const float* __restrict__ Wc2,
                        const float* __restrict__ bc2) {
    const int tid = blockIdx.x * blockDim.x + threadIdx.x;
    if (tid == 0) { g_params[1] = bc2[0]; g_params[2] = bc2[1]; g_params[3] = bc2[2]; }
    const int n1 = 64 * 40, n2 = 16 * 72, n3 = 64 * 40, n4 = 8 * 72;
    for (int i = tid; i < n1 + n2 + n3 + n4; i += blockDim.x * gridDim.x) {
        float v; int hiOff, loOff;
        if (i < n1) {
            int n = i / 40, k = i % 40;
            v = (k < 27) ? W1[k * 64 + n] : 0.0f;
            hiOff = (B1HI - BOFF) + i * 2; loOff = (B1LO - BOFF) + i * 2;
        } else if (i < n1 + n2) {
            int j = i - n1, n = j / 72, k = j % 72;
            v = (k < 64) ? W2[k * 16 + n] : 0.0f;
            hiOff = (B2HI - BOFF) + j * 2; loOff = (B2LO - BOFF) + j * 2;
        } else if (i < n1 + n2 + n3) {
            int j = i - n1 - n2, n = j / 40, k = j % 40;
            v = (k >= 1 && k < 16) ? Wc1[(k - 1) * 64 + n] : 0.0f;   // ynm folded into bias
            hiOff = (B3HI - BOFF) + j * 2; loOff = (B3LO - BOFF) + j * 2;
        } else {
            int j = i - n1 - n2 - n3, n = j / 72, k = j % 72;
            v = (n < 3 && k < 64) ? Wc2[k * 3 + n] : 0.0f;
            hiOff = (B4HI - BOFF) + j * 2; loOff = (B4LO - BOFF) + j * 2;
        }
        __nv_bfloat16 hi = __float2bfloat16(v);
        __nv_bfloat16 lo = __float2bfloat16(v - __bfloat162float(hi));
        *(__nv_bfloat16*)(g_B + hiOff) = hi;
        *(__nv_bfloat16*)(g_B + loOff) = lo;
    }
}

// ---- render ----
__global__ void __launch_bounds__(128, 4) nerf_mma5_kernel(
    const float* __restrict__ rays_o, const float* __restrict__ rays_d,
    const float* __restrict__ tnoise, const float* __restrict__ aabb,
    const float* __restrict__ b1, const float* __restrict__ b2,
    const float* __restrict__ bc1, const float* __restrict__ Wc1,
    float* __restrict__ out) {
    extern __shared__ __align__(16) unsigned char sm[];
    const uint32_t base = smem_u32(sm);
    const int tid = threadIdx.x, lane = tid & 31, wid = tid >> 5;
    const int g = lane >> 2, tg = lane & 3;
    const int m0 = wid * 32;

    // prologue: weights + biases
    {
        const int4* src = (const int4*)g_B;
        int4* dst = (int4*)(sm + BOFF);
        for (int i = tid; i < BBYTES / 16; i += 128) dst[i] = src[i];
        if (tid < 64) stsf(base + BIAS1 + 4 * tid, b1[tid]);
        if (tid < 16) stsf(base + BIAS2 + 4 * tid, b2[tid]);
    }
    const float ax0 = aabb[0], ay0 = aabb[1], az0 = aabb[2];
    const float ax1 = aabb[3], ay1 = aabb[4], az1 = aabb[5];
    const float p1 = g_params[1], p2 = g_params[2], p3 = g_params[3];
    __syncthreads();

    // per-lane ldmatrix address components
    const uint32_t arow = (uint32_t)((lane & 7) + ((lane >> 3) & 1) * 8);
    const uint32_t ak   = (uint32_t)(((lane >> 4) & 1) * 16);
    const uint32_t bn32 = (uint32_t)(((lane & 7) + ((lane >> 4) & 1) * 8) * S32
                                     + ((lane >> 3) & 1) * 16);
    const uint32_t bn64 = (uint32_t)(((lane & 7) + ((lane >> 4) & 1) * 8) * S64
                                     + ((lane >> 3) & 1) * 16);
    const uint32_t bn8  = (uint32_t)((lane & 7) * S64 + ((lane >> 3) & 1) * 16);

    for (int rr = 0; rr < RAYS_PER_BLK; ++rr) {
        const int ray = blockIdx.x * RAYS_PER_BLK + rr;

        // ---- ray setup (thread = sample row tid) ----
        const float ox = rays_o[3 * ray], oy = rays_o[3 * ray + 1], oz = rays_o[3 * ray + 2];
        const float dx = rays_d[3 * ray], dy = rays_d[3 * ray + 1], dz = rays_d[3 * ray + 2];
        const float ix = 1.0f / dx, iy = 1.0f / dy, iz = 1.0f / dz;
        const float t0x = (ax0 - ox) * ix, t1x = (ax1 - ox) * ix;
        const float t0y = (ay0 - oy) * iy, t1y = (ay1 - oy) * iy;
        const float t0z = (az0 - oz) * iz, t1z = (az1 - oz) * iz;
        float tn = fmaxf(fmaxf(fminf(t0x, t1x), fminf(t0y, t1y)), fminf(t0z, t1z));
        tn = fmaxf(tn, 0.0f);
        float tf = fminf(fminf(fmaxf(t0x, t1x), fmaxf(t0y, t1y)), fmaxf(t0z, t1z));
        float act;
        if (tf > tn) { act = 1.0f; } else { act = 0.0f; tn = 0.0f; tf = 0.0f; }
        const float span = tf - tn;
        const float dnorm = sqrtf(dx * dx + dy * dy + dz * dz);

        const float n0 = tnoise[tid * N_RAYS_C + ray];
        const float n1 = (tid < 127) ? tnoise[(tid + 1) * N_RAYS_C + ray] : 0.0f;
        const float ts  = tn + span * (((float)tid + n0) * (1.0f / 128.0f));
        const float ts1 = tn + span * (((float)tid + 1.0f + n1) * (1.0f / 128.0f));
        const float delta = (tid < 127) ? (ts1 - ts) : (tf * 10.0f - ts);

        const float idn = 1.0f / dnorm;
        const float c1 = 0.4886025119029199f;
        const float y0 = 0.28209479177387814f, y1 = c1 * dy * idn;
        const float y2 = c1 * dz * idn,        y3 = c1 * dx * idn;

        // per-ray fused color-layer bias: bc1 + ynm @ Wc1[15:19]  (fp32, exact)
        if (tid < 64) {
            const float s = bc1[tid]
                          + y0 * Wc1[15 * 64 + tid] + y1 * Wc1[16 * 64 + tid]
                          + y2 * Wc1[17 * 64 + tid] + y3 * Wc1[18 * 64 + tid];
            stsf(base + BIAS3 + 4 * tid, s);
        }

        {   // posenc -> packed regs -> A32 row tid via 4+4 STS.128
            float e[28];
            const float px = ox + ts * dx, py = oy + ts * dy, pz = oz + ts * dz;
            const float xnx = 2.0f * (px - ax0) / (ax1 - ax0) - 1.0f;
            const float xny = 2.0f * (py - ay0) / (ay1 - ay0) - 1.0f;
            const float xnz = 2.0f * (pz - az0) / (az1 - az0) - 1.0f;
            e[0] = xnx; e[1] = xny; e[2] = xnz;
            float f = 3.14159265358979323846f;
            #pragma unroll
            for (int k = 0; k < 4; ++k) {
                float sx, cx, sy, cy, sz, cz;
                __sincosf(f * xnx, &sx, &cx);
                __sincosf(f * xny, &sy, &cy);
                __sincosf(f * xnz, &sz, &cz);
                e[3 + 6 * k + 0] = sx; e[3 + 6 * k + 1] = sy; e[3 + 6 * k + 2] = sz;
                e[6 + 6 * k + 0] = cx; e[6 + 6 * k + 1] = cy; e[6 + 6 * k + 2] = cz;
                f *= 2.0f;
            }
            e[27] = 0.0f;
            uint32_t hp[16], lp[16];
            #pragma unroll
            for (int p = 0; p < 14; ++p) split2(e[2 * p], e[2 * p + 1], hp[p], lp[p]);
            hp[14] = hp[15] = 0u; lp[14] = lp[15] = 0u;   // cols 28..31 zero
            const uint32_t rb = (uint32_t)tid * S32;
            #pragma unroll
            for (int q = 0; q < 4; ++q) {
                sts128(base + A32HI + rb + 16 * q, hp[4 * q], hp[4 * q + 1], hp[4 * q + 2], hp[4 * q + 3]);
                sts128(base + A32LO + rb + 16 * q, lp[4 * q], lp[4 * q + 1], lp[4 * q + 2], lp[4 * q + 3]);
            }
        }
        __syncthreads();   // A32 + BIAS3 visible to all warps

        float acc[2][8][4];
        // ---- stage 1: posenc @ W1 (K32,N64) ----
        {
            uint32_t a1h[2][2][4], a1l[2][2][4];
            #pragma unroll
            for (int mt = 0; mt < 2; ++mt) {
                const uint32_t ao = (uint32_t)((m0 + 16 * mt) * S32) + arow * S32 + ak;
                #pragma unroll
                for (int kb = 0; kb < 2; ++kb) {
                    ldm_x4(base + A32HI + ao + kb * 32, a1h[mt][kb]);
                    ldm_x4(base + A32LO + ao + kb * 32, a1l[mt][kb]);
                }
            }
            #pragma unroll
            for (int mt = 0; mt < 2; ++mt)
                #pragma unroll
                for (int nt = 0; nt < 8; ++nt)
                    acc[mt][nt][0] = acc[mt][nt][1] = acc[mt][nt][2] = acc[mt][nt][3] = 0.f;
            #pragma unroll
            for (int np = 0; np < 4; ++np) {
                #pragma unroll
                for (int kb = 0; kb < 2; ++kb) {
                    uint32_t bh[4], bl[4];
                    const uint32_t bo = bn32 + (uint32_t)(np * 16 * S32) + kb * 32;
                    ldm_x4(base + B1HI + bo, bh);
                    #pragma unroll
                    for (int mt = 0; mt < 2; ++mt) {
                        MMA(acc[mt][2 * np],     a1h[mt][kb], bh[0], bh[1]);
                        MMA(acc[mt][2 * np + 1], a1h[mt][kb], bh[2], bh[3]);
                        MMA(acc[mt][2 * np],     a1l[mt][kb], bh[0], bh[1]);
                        MMA(acc[mt][2 * np + 1], a1l[mt][kb], bh[2], bh[3]);
                    }
                    ldm_x4(base + B1LO + bo, bl);
                    #pragma unroll
                    for (int mt = 0; mt < 2; ++mt) {
                        MMA(acc[mt][2 * np],     a1h[mt][kb], bl[0], bl[1]);
                        MMA(acc[mt][2 * np + 1], a1h[mt][kb], bl[2], bl[3]);
                    }
                }
            }
        }

        // ---- epilogue 1: bias+relu -> stage2 A frags (registers) ----
        uint32_t f2h[2][4][4], f2l[2][4][4];
        #pragma unroll
        for (int nt = 0; nt < 8; ++nt) {
            const int c = nt * 8 + tg * 2;
            const float bb0 = ldsf(base + BIAS1 + 4 * c);
            const float bb1 = ldsf(base + BIAS1 + 4 * c + 4);
            const int kb = nt >> 1, hb = (nt & 1) * 2;
            #pragma unroll
            for (int mt = 0; mt < 2; ++mt) {
                float* d = acc[mt][nt];
                split2(fmaxf(d[0] + bb0, 0.f), fmaxf(d[1] + bb1, 0.f),
                       f2h[mt][kb][hb], f2l[mt][kb][hb]);
                split2(fmaxf(d[2] + bb0, 0.f), fmaxf(d[3] + bb1, 0.f),
                       f2h[mt][kb][hb + 1], f2l[mt][kb][hb + 1]);
            }
        }

        // ---- stage 2: h @ W2 (K64,N16) ----
        #pragma unroll
        for (int mt = 0; mt < 2; ++mt)
            #pragma unroll
            for (int nt = 0; nt < 2; ++nt)
                acc[mt][nt][0] = acc[mt][nt][1] = acc[mt][nt][2] = acc[mt][nt][3] = 0.f;
        #pragma unroll
        for (int kb = 0; kb < 4; ++kb) {
            uint32_t bh[4], bl[4];
            ldm_x4(base + B2HI + bn64 + kb * 32, bh);
            #pragma unroll
            for (int mt = 0; mt < 2; ++mt) {
                MMA(acc[mt][0], f2h[mt][kb], bh[0], bh[1]);
                MMA(acc[mt][1], f2h[mt][kb], bh[2], bh[3]);
                MMA(acc[mt][0], f2l[mt][kb], bh[0], bh[1]);
                MMA(acc[mt][1], f2l[mt][kb], bh[2], bh[3]);
            }
            ldm_x4(base + B2LO + bn64 + kb * 32, bl);
            #pragma unroll
            for (int mt = 0; mt < 2; ++mt) {
                MMA(acc[mt][0], f2h[mt][kb], bl[0], bl[1]);
                MMA(acc[mt][1], f2h[mt][kb], bl[2], bl[3]);
            }
        }

        // ---- epilogue 2: sigma + stage3 A frags (K=16) ----
        uint32_t a3h[2][4], a3l[2][4];
        #pragma unroll
        for (int nt = 0; nt < 2; ++nt) {
            const int c = nt * 8 + tg * 2;
            const float bb0 = ldsf(base + BIAS2 + 4 * c);
            const float bb1 = ldsf(base + BIAS2 + 4 * c + 4);
            const int hb = nt * 2;
            #pragma unroll
            for (int mt = 0; mt < 2; ++mt) {
                float* d = acc[mt][nt];
                const float v0 = d[0] + bb0, v1 = d[1] + bb1;
                const float v2 = d[2] + bb0, v3 = d[3] + bb1;
                split2(v0, v1, a3h[mt][hb], a3l[mt][hb]);
                split2(v2, v3, a3h[mt][hb + 1], a3l[mt][hb + 1]);
                if (nt == 0 && tg == 0) {
                    stsf(base + SIGO + 4 * (m0 + 16 * mt + g), v0);
                    stsf(base + SIGO + 4 * (m0 + 16 * mt + g + 8), v2);
                }
            }
        }

        // ---- stage 3: feat @ Wc1[0:15] (K16,N64) ----
        #pragma unroll
        for (int mt = 0; mt < 2; ++mt)
            #pragma unroll
            for (int nt = 0; nt < 8; ++nt)
                acc[mt][nt][0] = acc[mt][nt][1] = acc[mt][nt][2] = acc[mt][nt][3] = 0.f;
        #pragma unroll
        for (int np = 0; np < 4; ++np) {
            uint32_t bh[4], bl[4];
            const uint32_t bo = bn32 + (uint32_t)(np * 16 * S32);
            ldm_x4(base + B3HI + bo, bh);
            #pragma unroll
            for (int mt = 0; mt < 2; ++mt) {
                MMA(acc[mt][2 * np],     a3h[mt], bh[0], bh[1]);
                MMA(acc[mt][2 * np + 1], a3h[mt], bh[2], bh[3]);
                MMA(acc[mt][2 * np],     a3l[mt], bh[0], bh[1]);
                MMA(acc[mt][2 * np + 1], a3l[mt], bh[2], bh[3]);
            }
            ldm_x4(base + B3LO + bo, bl);
            #pragma unroll
            for (int mt = 0; mt < 2; ++mt) {
                MMA(acc[mt][2 * np],     a3h[mt], bl[0], bl[1]);
                MMA(acc[mt][2 * np + 1], a3h[mt], bl[2], bl[3]);
            }
        }

        // ---- epilogue 3: (per-ray fused bias)+relu -> stage4 A frags ----
        #pragma unroll
        for (int nt = 0; nt < 8; ++nt) {
            const int c = nt * 8 + tg * 2;
            const float bb0 = ldsf(base + BIAS3 + 4 * c);
            const float bb1 = ldsf(base + BIAS3 + 4 * c + 4);
            const int kb = nt >> 1, hb = (nt & 1) * 2;
            #pragma unroll
            for (int mt = 0; mt < 2; ++mt) {
                float* d = acc[mt][nt];
                split2(fmaxf(d[0] + bb0, 0.f), fmaxf(d[1] + bb1, 0.f),
                       f2h[mt][kb][hb], f2l[mt][kb][hb]);
                split2(fmaxf(d[2] + bb0, 0.f), fmaxf(d[3] + bb1, 0.f),
                       f2h[mt][kb][hb + 1], f2l[mt][kb][hb + 1]);
            }
        }

        // ---- stage 4: hc @ Wc2 (K64,N8) ----
        float a4[2][4];
        a4[0][0] = a4[0][1] = a4[0][2] = a4[0][3] = 0.f;
        a4[1][0] = a4[1][1] = a4[1][2] = a4[1][3] = 0.f;
        #pragma unroll
        for (int kb = 0; kb < 4; ++kb) {
            uint32_t bh[2], bl[2];
            ldm_x2(base + B4HI + bn8 + kb * 32, bh);
            #pragma unroll
            for (int mt = 0; mt < 2; ++mt) {
                MMA(a4[mt], f2h[mt][kb], bh[0], bh[1]);
                MMA(a4[mt], f2l[mt][kb], bh[0], bh[1]);
            }
            ldm_x2(base + B4LO + bn8 + kb * 32, bl);
            #pragma unroll
            for (int mt = 0; mt < 2; ++mt)
                MMA(a4[mt], f2h[mt][kb], bl[0], bl[1]);
        }
        if (tg < 2) {
            #pragma unroll
            for (int mt = 0; mt < 2; ++mt) {
                const int rA = m0 + 16 * mt + g, rB = rA + 8;
                stsf(base + RGBO + rA * 16 + tg * 8,     a4[mt][0]);
                stsf(base + RGBO + rA * 16 + tg * 8 + 4, a4[mt][1]);
                stsf(base + RGBO + rB * 16 + tg * 8,     a4[mt][2]);
                stsf(base + RGBO + rB * 16 + tg * 8 + 4, a4[mt][3]);
            }
        }
        __syncthreads();

        // ---- transmittance scan + composite (thread = sample tid) ----
        const float sigma = __expf(ldsf(base + SIGO + 4 * tid));
        const float sd = sigma * delta * dnorm;
        float x = sd;
        #pragma unroll
        for (int off = 1; off < 32; off <<= 1) {
            float v = __shfl_up_sync(0xffffffffu, x, off);
            if (lane >= off) x += v;
        }
        if (lane == 31) stsf(base + SCANW + 4 * wid, x);
        __syncthreads();
        float pre = 0.0f;
        #pragma unroll
        for (int w = 0; w < 4; ++w) if (w < wid) pre += ldsf(base + SCANW + 4 * w);
        const float excl = (x + pre) - sd;
        const float trans = __expf(-excl);
        const float alpha = 1.0f - __expf(-sd);
        const float wgt = trans * alpha * act;

        const float rC = 1.0f / (1.0f + __expf(-(ldsf(base + RGBO + tid * 16)     + p1)));
        const float gC = 1.0f / (1.0f + __expf(-(ldsf(base + RGBO + tid * 16 + 4) + p2)));
        const float bC = 1.0f / (1.0f + __expf(-(ldsf(base + RGBO + tid * 16 + 8) + p3)));

        float cr = wgt * rC, cg = wgt * gC, cb = wgt * bC, ca = wgt;
        #pragma unroll
        for (int off = 16; off > 0; off >>= 1) {
            cr += __shfl_xor_sync(0xffffffffu, cr, off);
            cg += __shfl_xor_sync(0xffffffffu, cg, off);
            cb += __shfl_xor_sync(0xffffffffu, cb, off);
            ca += __shfl_xor_sync(0xffffffffu, ca, off);
        }
        if (lane == 0) {
            stsf(base + PARTO + (wid * 4 + 0) * 4, cr);
            stsf(base + PARTO + (wid * 4 + 1) * 4, cg);
            stsf(base + PARTO + (wid * 4 + 2) * 4, cb);
            stsf(base + PARTO + (wid * 4 + 3) * 4, ca);
        }
        __syncthreads();
        if (tid == 0) {
            float4 o4 = make_float4(0.f, 0.f, 0.f, 0.f);
            #pragma unroll
            for (int w = 0; w < 4; ++w) {
                o4.x += ldsf(base + PARTO + (w * 4 + 0) * 4);
                o4.y += ldsf(base + PARTO + (w * 4 + 1) * 4);
                o4.z += ldsf(base + PARTO + (w * 4 + 2) * 4);
                o4.w += ldsf(base + PARTO + (w * 4 + 3) * 4);
            }
            *(float4*)(out + ray * 4) = o4;
        }
        __syncthreads();
    }
}

extern "C" void kernel_launch(void* const* d_in, const int* in_sizes, int n_in,
                              void* d_out, int out_size) {
    const float* rays_o = (const float*)d_in[0];
    const float* rays_d = (const float*)d_in[1];
    const float* tnoise = (const float*)d_in[2];
    const float* aabb   = (const float*)d_in[3];
    const float* W1     = (const float*)d_in[4];
    const float* b1     = (const float*)d_in[5];
    const float* W2     = (const float*)d_in[6];
    const float* b2     = (const float*)d_in[7];
    const float* Wc1    = (const float*)d_in[8];
    const float* bc1    = (const float*)d_in[9];
    const float* Wc2    = (const float*)d_in[10];
    const float* bc2    = (const float*)d_in[11];
    float* out = (float*)d_out;

    k_setup<<<8, 256>>>(W1, W2, Wc1, Wc2, bc2);
    cudaFuncSetAttribute(nerf_mma5_kernel, cudaFuncAttributeMaxDynamicSharedMemorySize, SMEM_DYN);
    nerf_mma5_kernel<<<NBLK, 128, SMEM_DYN>>>(rays_o, rays_d, tnoise, aabb,
                                              b1, b2, bc1, Wc1, out);
}